// round 6
// baseline (speedup 1.0000x reference)
#include <cuda_runtime.h>
#include <math.h>
#include <stdint.h>

#define BATCH 4096
#define TT    15
#define EMBD  300
#define HID   512
#define G3    1536
#define DD    1024
#define BT    (BATCH*TT)
#define VOCAB 12000
#define BH    (BATCH*HID)

#define SROW      36                 // smem row stride in u32 (32 + 4 pad)
#define STAGE_U32 (128*SROW)
#define SMEM_B    (2*2*STAGE_U32*4)  // tgemm/attn_w smem: 73728 B

// fused recurrence: A(64 rows) + B(384 rows) per stage, 3 stages (cp.async ring)
#define R_A_U32   (64*SROW)          // 2304
#define R_B_U32   (384*SROW)         // 13824
#define R_STAGE   (R_A_U32 + R_B_U32)  // 16128 u32
#define R_STAGES  3
#define R_SMEM    (R_STAGES*R_STAGE*4) // 193536 B

// ---------------- scratch -----------------------------------------------------
__device__ float    g_git_f[(size_t)VOCAB * G3];     // gi table fwd (incl b_ih)
__device__ float    g_git_b[(size_t)VOCAB * G3];
__device__ uint32_t g_whht[(size_t)2 * 16 * G3 * 32]; // pre-permuted tf32 w_hh
__device__ uint32_t g_wlt [(size_t)32 * DD * 32];     // pre-permuted tf32 w_local
__device__ uint32_t g_htf [(size_t)2 * 2 * BH];       // permuted tf32 h, [dir][buf]
__device__ float    g_yword[(size_t)BT * DD];
__device__ float    g_ypool[BATCH * DD];
__device__ float    g_gw  [BATCH * DD];
__device__ float    g_wraw[BT];

// ---------------- TF32 helpers -------------------------------------------------
__device__ __forceinline__ uint32_t f2tf(float x) {
    uint32_t r; asm("cvt.rna.tf32.f32 %0, %1;" : "=r"(r) : "f"(x)); return r;
}
__device__ __forceinline__ void mma8(float* c,
    uint32_t a0, uint32_t a1, uint32_t a2, uint32_t a3,
    uint32_t b0, uint32_t b1)
{
    asm volatile(
        "mma.sync.aligned.m16n8k8.row.col.f32.tf32.tf32.f32 "
        "{%0,%1,%2,%3},{%4,%5,%6,%7},{%8,%9},{%0,%1,%2,%3};"
        : "+f"(c[0]), "+f"(c[1]), "+f"(c[2]), "+f"(c[3])
        : "r"(a0), "r"(a1), "r"(a2), "r"(a3), "r"(b0), "r"(b1));
}
__device__ __forceinline__ float sigm(float x) { return 1.f / (1.f + expf(-x)); }
__device__ __forceinline__ void cp16(uint32_t saddr, const void* g) {
    asm volatile("cp.async.cg.shared.global [%0], [%1], 16;" :: "r"(saddr), "l"(g));
}

// ---------------- weight prep (one-time, permuted tf32) ------------------------
// slot p(c) = (c%4)*8 + c/4 within each 32-wide k-chunk
__global__ void prep_whh(const float* __restrict__ wf, const float* __restrict__ wb,
                         uint32_t* __restrict__ out)
{
    const int idx = blockIdx.x * 256 + threadIdx.x;      // 2*1536*512
    const int per = G3 * HID;
    const int dir = idx / per, rem = idx % per;
    const int row = rem >> 9, k = rem & 511;
    const int kc = k >> 5, c = k & 31;
    const int p = (c & 3) * 8 + (c >> 2);
    const float* W = dir ? wb : wf;
    out[(((size_t)dir * 16 + kc) * G3 + row) * 32 + p] = f2tf(W[(size_t)row * HID + k]);
}
__global__ void prep_wl(const float* __restrict__ wl, uint32_t* __restrict__ out)
{
    const int idx = blockIdx.x * 256 + threadIdx.x;      // 1024*1024
    const int row = idx >> 10, k = idx & 1023;
    const int kc = k >> 5, c = k & 31;
    const int p = (c & 3) * 8 + (c >> 2);
    out[((size_t)kc * DD + row) * 32 + p] = f2tf(wl[idx]);
}

// ================= generic 128x128 TF32 GEMM (git + gw) ========================
__device__ __forceinline__ void stage_load(
    const float* const* aptr, const float* const* wptr,
    int k, int K, float4* ra, float4* rb)
{
    const float4 z4 = make_float4(0.f, 0.f, 0.f, 0.f);
    const bool v = (k < K);
    #pragma unroll
    for (int i = 0; i < 4; i++) {
        ra[i] = v ? *(const float4*)(aptr[i] + k) : z4;
        rb[i] = v ? *(const float4*)(wptr[i] + k) : z4;
    }
}
__device__ __forceinline__ void stage_store(
    uint32_t* dst, int lr, int lc4, const float4* ra, const float4* rb)
{
    uint32_t* db = dst + STAGE_U32;
    #pragma unroll
    for (int i = 0; i < 4; i++) {
        const int base = (lr + i * 32) * SROW + lc4;
        dst[base +  0] = f2tf(ra[i].x);
        dst[base +  8] = f2tf(ra[i].y);
        dst[base + 16] = f2tf(ra[i].z);
        dst[base + 24] = f2tf(ra[i].w);
        db [base +  0] = f2tf(rb[i].x);
        db [base +  8] = f2tf(rb[i].y);
        db [base + 16] = f2tf(rb[i].z);
        db [base + 24] = f2tf(rb[i].w);
    }
}
__device__ __forceinline__ void mm_tile(
    const uint32_t* As, const uint32_t* Bs,
    int wm0, int wn0, int g, int q, float (*c)[8][4])
{
    const uint4* As4 = (const uint4*)As;
    const uint4* Bs4 = (const uint4*)Bs;
    #pragma unroll
    for (int h = 0; h < 2; h++) {
        const int fo = q * 2 + h;
        const uint4 aL0 = As4[(wm0 + g     ) * 9 + fo];
        const uint4 aH0 = As4[(wm0 + g +  8) * 9 + fo];
        const uint4 aL1 = As4[(wm0 + g + 16) * 9 + fo];
        const uint4 aH1 = As4[(wm0 + g + 24) * 9 + fo];
        uint4 bf[8];
        #pragma unroll
        for (int nt = 0; nt < 8; nt++)
            bf[nt] = Bs4[(wn0 + nt * 8 + g) * 9 + fo];
        #pragma unroll
        for (int s = 0; s < 2; s++) {
            const uint32_t A00 = s ? aL0.z : aL0.x;
            const uint32_t A20 = s ? aL0.w : aL0.y;
            const uint32_t A10 = s ? aH0.z : aH0.x;
            const uint32_t A30 = s ? aH0.w : aH0.y;
            const uint32_t A01 = s ? aL1.z : aL1.x;
            const uint32_t A21 = s ? aL1.w : aL1.y;
            const uint32_t A11 = s ? aH1.z : aH1.x;
            const uint32_t A31 = s ? aH1.w : aH1.y;
            #pragma unroll
            for (int nt = 0; nt < 8; nt++) {
                const uint32_t B0 = s ? bf[nt].z : bf[nt].x;
                const uint32_t B1 = s ? bf[nt].w : bf[nt].y;
                mma8(c[0][nt], A00, A10, A20, A30, B0, B1);
                mma8(c[1][nt], A01, A11, A21, A31, B0, B1);
            }
        }
    }
}

__global__ void __launch_bounds__(256) tgemm(
    const float* __restrict__ A,  const float* __restrict__ A2, int lda,
    const float* __restrict__ W,  const float* __restrict__ W2,
    const float* __restrict__ bias, const float* __restrict__ bias2,
    const float* __restrict__ wc,
    float* __restrict__ C, float* __restrict__ C2,
    int M, int N, int K, int epi)
{
    if (blockIdx.z == 1) { A = A2; W = W2; bias = bias2; C = C2; }
    extern __shared__ uint32_t sm[];

    const int tid  = threadIdx.x;
    const int lane = tid & 31, wid = tid >> 5;
    const int g = lane >> 2, q = lane & 3;
    const int wm0 = (wid & 3) * 32;
    const int wn0 = (wid >> 2) * 64;
    const int row0 = blockIdx.x * 128;
    const int col0 = blockIdx.y * 128;
    const int lr  = tid >> 3;
    const int lc4 = tid & 7;

    const float* aptr[4];
    const float* wptr[4];
    #pragma unroll
    for (int i = 0; i < 4; i++) {
        int ar = row0 + lr + i * 32;
        if (ar >= M) ar = M - 1;
        aptr[i] = A + (long)ar * lda;
        wptr[i] = W + (long)(col0 + lr + i * 32) * K;
    }

    float c[2][8][4];
    #pragma unroll
    for (int mt = 0; mt < 2; mt++)
        #pragma unroll
        for (int nt = 0; nt < 8; nt++)
            #pragma unroll
            for (int j = 0; j < 4; j++) c[mt][nt][j] = 0.f;

    float4 ra[4], rb[4];
    const int nk = (K + 31) / 32;

    stage_load(aptr, wptr, lc4 * 4, K, ra, rb);
    stage_store(sm, lr, lc4, ra, rb);
    __syncthreads();

    for (int it = 0; it < nk; it++) {
        const bool more = (it + 1 < nk);
        if (more) stage_load(aptr, wptr, (it + 1) * 32 + lc4 * 4, K, ra, rb);
        const uint32_t* cur = sm + (it & 1) * (2 * STAGE_U32);
        mm_tile(cur, cur + STAGE_U32, wm0, wn0, g, q, c);
        if (more) {
            stage_store(sm + ((it + 1) & 1) * (2 * STAGE_U32), lr, lc4, ra, rb);
            __syncthreads();
        }
    }

    #pragma unroll
    for (int mt = 0; mt < 2; mt++) {
        const int r = row0 + wm0 + mt * 16 + g;
        #pragma unroll
        for (int nt = 0; nt < 8; nt++) {
            const int n = col0 + wn0 + nt * 8 + q * 2;
            const float b0 = bias[n], b1 = bias[n + 1];
            float v00 = c[mt][nt][0] + b0, v01 = c[mt][nt][1] + b1;
            float v10 = c[mt][nt][2] + b0, v11 = c[mt][nt][3] + b1;
            if (epi == 1) {
                const float w0 = wc[n], w1 = wc[n + 1];
                v00 = tanhf(v00) * w0; v01 = tanhf(v01) * w1;
                v10 = tanhf(v10) * w0; v11 = tanhf(v11) * w1;
            }
            if (r < M)
                *(float2*)(C + (long)r * N + n) = make_float2(v00, v01);
            if (r + 8 < M)
                *(float2*)(C + (long)(r + 8) * N + n) = make_float2(v10, v11);
        }
    }
}

// ================= fused GRU recurrence step (cp.async pipeline) ===============
// CTA: 64 batch x 128 hidden, 3 gates. A = h_tf (permuted tf32), B = g_whht.
__global__ void __launch_bounds__(256) rec_step(
    const int* __restrict__ inds,
    const float* __restrict__ git_f, const float* __restrict__ git_b,
    const uint32_t* __restrict__ whht,
    const float* __restrict__ bhh_f, const float* __restrict__ bhh_b,
    uint32_t* __restrict__ htf,
    float* __restrict__ y_word, int t)
{
    const int dir = blockIdx.z;
    const int cur = t & 1, nxt = cur ^ 1;
    const float* git = dir ? git_b : git_f;
    const float* bhh = dir ? bhh_b : bhh_f;
    const int tt  = dir ? (TT - 1 - t) : t;
    const int off = dir ? HID : 0;
    const uint32_t* Wp    = whht + (size_t)dir * 16 * G3 * 32;
    const uint32_t* hprev = htf + ((size_t)dir * 2 + cur) * BH;
    uint32_t*       hnext = htf + ((size_t)dir * 2 + nxt) * BH;

    extern __shared__ uint32_t sm[];
    const uint32_t sbase = (uint32_t)__cvta_generic_to_shared(sm);

    const int tid  = threadIdx.x;
    const int lane = tid & 31, wid = tid >> 5;
    const int g = lane >> 2, q = lane & 3;
    const int wm0 = (wid & 1) * 32;       // 2 m-warps
    const int wn0 = (wid >> 1) * 32;      // 4 n-warps
    const int row0 = blockIdx.x * 64;     // batch tile
    const int col0 = blockIdx.y * 128;    // hidden tile

    // cp.async issue for one k-chunk kc into stage st
    auto issue = [&](int kc, int st) {
        const uint32_t s0 = sbase + st * R_STAGE * 4;
        // A: 64 rows x 8 units
        #pragma unroll
        for (int s = 0; s < 2; s++) {
            const int u = tid + s * 256;
            const int r = u >> 3, j = u & 7;
            cp16(s0 + (r * SROW + j * 4) * 4,
                 hprev + (size_t)(row0 + r) * HID + kc * 32 + j * 4);
        }
        // B: 384 rows x 8 units
        #pragma unroll
        for (int s = 0; s < 12; s++) {
            const int u = tid + s * 256;
            const int r = u >> 3, j = u & 7;           // r: 0..383
            const int gate = r >> 7, wi = r & 127;
            cp16(s0 + ((R_A_U32 + r * SROW + j * 4)) * 4,
                 Wp + ((size_t)kc * G3 + gate * HID + col0 + wi) * 32 + j * 4);
        }
        asm volatile("cp.async.commit_group;");
    };

    float c[3][2][4][4];
    #pragma unroll
    for (int gt = 0; gt < 3; gt++)
        #pragma unroll
        for (int mt = 0; mt < 2; mt++)
            #pragma unroll
            for (int nt = 0; nt < 4; nt++)
                #pragma unroll
                for (int j = 0; j < 4; j++) c[gt][mt][nt][j] = 0.f;

    const int nk = HID / 32;  // 16
    issue(0, 0);
    issue(1, 1);

    for (int it = 0; it < nk; it++) {
        if (it + 1 < nk) asm volatile("cp.async.wait_group 1;");
        else             asm volatile("cp.async.wait_group 0;");
        __syncthreads();
        if (it + 2 < nk) issue(it + 2, (it + 2) % R_STAGES);

        const uint32_t* curS = sm + (it % R_STAGES) * R_STAGE;
        const uint4* As4 = (const uint4*)curS;
        const uint4* Bs4 = (const uint4*)(curS + R_A_U32);
        #pragma unroll
        for (int h = 0; h < 2; h++) {
            const int fo = q * 2 + h;
            const uint4 aL0 = As4[(wm0 + g     ) * 9 + fo];
            const uint4 aH0 = As4[(wm0 + g +  8) * 9 + fo];
            const uint4 aL1 = As4[(wm0 + g + 16) * 9 + fo];
            const uint4 aH1 = As4[(wm0 + g + 24) * 9 + fo];
            uint4 bf[3][4];
            #pragma unroll
            for (int gt = 0; gt < 3; gt++)
                #pragma unroll
                for (int nt = 0; nt < 4; nt++)
                    bf[gt][nt] = Bs4[(gt * 128 + wn0 + nt * 8 + g) * 9 + fo];
            #pragma unroll
            for (int s = 0; s < 2; s++) {
                const uint32_t A00 = s ? aL0.z : aL0.x;
                const uint32_t A20 = s ? aL0.w : aL0.y;
                const uint32_t A10 = s ? aH0.z : aH0.x;
                const uint32_t A30 = s ? aH0.w : aH0.y;
                const uint32_t A01 = s ? aL1.z : aL1.x;
                const uint32_t A21 = s ? aL1.w : aL1.y;
                const uint32_t A11 = s ? aH1.z : aH1.x;
                const uint32_t A31 = s ? aH1.w : aH1.y;
                #pragma unroll
                for (int gt = 0; gt < 3; gt++)
                    #pragma unroll
                    for (int nt = 0; nt < 4; nt++) {
                        const uint32_t B0 = s ? bf[gt][nt].z : bf[gt][nt].x;
                        const uint32_t B1 = s ? bf[gt][nt].w : bf[gt][nt].y;
                        mma8(c[gt][0][nt], A00, A10, A20, A30, B0, B1);
                        mma8(c[gt][1][nt], A01, A11, A21, A31, B0, B1);
                    }
            }
        }
    }

    // ---- GRU cell epilogue ----
    #pragma unroll
    for (int mt = 0; mt < 2; mt++) {
        #pragma unroll
        for (int rr = 0; rr < 2; rr++) {
            const int b = row0 + wm0 + mt * 16 + g + rr * 8;
            const int tok = inds[b * TT + tt];
            const float* gib = git + (long)tok * G3;
            #pragma unroll
            for (int nt = 0; nt < 4; nt++) {
                const int hg = col0 + wn0 + nt * 8 + q * 2;
                const int j0 = rr * 2;
                #pragma unroll
                for (int e = 0; e < 2; e++) {
                    const int hh = hg + e;
                    const int cc = hh & 31;
                    const long off_tf = (long)b * HID + (hh >> 5) * 32
                                      + (cc & 3) * 8 + (cc >> 2);
                    const float gir = gib[hh];
                    const float giz = gib[HID + hh];
                    const float gin = gib[2 * HID + hh];
                    const float ghr = c[0][mt][nt][j0 + e] + bhh[hh];
                    const float ghz = c[1][mt][nt][j0 + e] + bhh[HID + hh];
                    const float ghn = c[2][mt][nt][j0 + e] + bhh[2 * HID + hh];
                    const float hp = __uint_as_float(hprev[off_tf]);
                    const float r = sigm(gir + ghr);
                    const float z = sigm(giz + ghz);
                    const float n = tanhf(gin + r * ghn);
                    const float hnew = (1.f - z) * n + z * hp;
                    hnext[off_tf] = f2tf(hnew);
                    y_word[(long)(b * TT + tt) * DD + off + hh] = hnew;
                }
            }
        }
    }
}

// ---------------- fused attention logits (B from pre-permuted w_local) ---------
__global__ void __launch_bounds__(256) attn_w(
    const float* __restrict__ yw, const uint32_t* __restrict__ wlt,
    const float* __restrict__ bl, const float* __restrict__ gw,
    const float* __restrict__ bc, float* __restrict__ wraw)
{
    extern __shared__ uint32_t sm[];
    __shared__ float red[128][9];

    const int tid  = threadIdx.x;
    const int lane = tid & 31, wid = tid >> 5;
    const int g = lane >> 2, q = lane & 3;
    const int wm0 = (wid & 3) * 32;
    const int wn0 = (wid >> 2) * 64;
    const int row0 = blockIdx.x * 128;
    const int lr  = tid >> 3;
    const int lc4 = tid & 7;

    const float* aptr[4];
    #pragma unroll
    for (int i = 0; i < 4; i++)
        aptr[i] = yw + (long)(row0 + lr + i * 32) * DD;

    int rbi0[2], rbi1[2];
    #pragma unroll
    for (int mt = 0; mt < 2; mt++) {
        const int r = row0 + wm0 + mt * 16 + g;
        rbi0[mt] = r / TT;
        rbi1[mt] = (r + 8) / TT;
    }
    float rowsum[2][2] = {{0.f, 0.f}, {0.f, 0.f}};

    const int nk = DD / 32;   // k-chunks per column pass

    for (int ct = 0; ct < DD / 128; ct++) {
        const int col0 = ct * 128;

        float c[2][8][4];
        #pragma unroll
        for (int mt = 0; mt < 2; mt++)
            #pragma unroll
            for (int nt = 0; nt < 8; nt++)
                #pragma unroll
                for (int j = 0; j < 4; j++) c[mt][nt][j] = 0.f;

        float4 ra[4];
        uint4  rbu[4];
        // prefetch k-chunk 0
        #pragma unroll
        for (int i = 0; i < 4; i++) {
            ra[i]  = *(const float4*)(aptr[i] + lc4 * 4);
            rbu[i] = *(const uint4*)(wlt + ((size_t)0 * DD + col0 + lr + i * 32) * 32 + lc4 * 4);
        }
        // store stage 0
        {
            uint32_t* sa = sm;
            uint32_t* sb = sm + STAGE_U32;
            #pragma unroll
            for (int i = 0; i < 4; i++) {
                const int base = (lr + i * 32) * SROW + lc4;
                sa[base+0]=f2tf(ra[i].x); sa[base+8]=f2tf(ra[i].y);
                sa[base+16]=f2tf(ra[i].z); sa[base+24]=f2tf(ra[i].w);
                *(uint4*)&sb[(lr + i * 32) * SROW + lc4 * 4] = rbu[i];
            }
        }
        __syncthreads();

        for (int it = 0; it < nk; it++) {
            const bool more = (it + 1 < nk);
            if (more) {
                const int k = (it + 1) * 32 + lc4 * 4;
                #pragma unroll
                for (int i = 0; i < 4; i++) {
                    ra[i]  = *(const float4*)(aptr[i] + k);
                    rbu[i] = *(const uint4*)(wlt + ((size_t)(it + 1) * DD + col0 + lr + i * 32) * 32 + lc4 * 4);
                }
            }
            const uint32_t* curS = sm + (it & 1) * (2 * STAGE_U32);
            mm_tile(curS, curS + STAGE_U32, wm0, wn0, g, q, c);
            if (more) {
                uint32_t* nx = sm + ((it + 1) & 1) * (2 * STAGE_U32);
                uint32_t* sa = nx;
                uint32_t* sb = nx + STAGE_U32;
                #pragma unroll
                for (int i = 0; i < 4; i++) {
                    const int base = (lr + i * 32) * SROW + lc4;
                    sa[base+0]=f2tf(ra[i].x); sa[base+8]=f2tf(ra[i].y);
                    sa[base+16]=f2tf(ra[i].z); sa[base+24]=f2tf(ra[i].w);
                    *(uint4*)&sb[(lr + i * 32) * SROW + lc4 * 4] = rbu[i];
                }
                __syncthreads();
            }
        }

        #pragma unroll
        for (int mt = 0; mt < 2; mt++) {
            #pragma unroll
            for (int nt = 0; nt < 8; nt++) {
                const int n = col0 + wn0 + nt * 8 + q * 2;
                const float bb0 = bl[n], bb1 = bl[n + 1];
                rowsum[mt][0] += tanhf(c[mt][nt][0] + bb0) * gw[(long)rbi0[mt] * DD + n]
                               + tanhf(c[mt][nt][1] + bb1) * gw[(long)rbi0[mt] * DD + n + 1];
                rowsum[mt][1] += tanhf(c[mt][nt][2] + bb0) * gw[(long)rbi1[mt] * DD + n]
                               + tanhf(c[mt][nt][3] + bb1) * gw[(long)rbi1[mt] * DD + n + 1];
            }
        }
        __syncthreads();
    }

    const int rc = (wid >> 2) * 4 + q;
    #pragma unroll
    for (int mt = 0; mt < 2; mt++) {
        red[wm0 + mt * 16 + g    ][rc] = rowsum[mt][0];
        red[wm0 + mt * 16 + g + 8][rc] = rowsum[mt][1];
    }
    __syncthreads();
    if (tid < 128) {
        float s = 0.f;
        #pragma unroll
        for (int x = 0; x < 8; x++) s += red[tid][x];
        wraw[row0 + tid] = s + bc[0];
    }
}

// ---------------- small kernels ------------------------------------------------
__global__ void zero_htf(uint32_t* __restrict__ htf)
{
    const size_t i = (size_t)blockIdx.x * 256 + threadIdx.x;
    htf[i] = 0u;   // zeros all dir/buf copies
}

__global__ void maxpool(const int* __restrict__ inds,
                        const float* __restrict__ y_word,
                        float* __restrict__ y_pool)
{
    const int idx = blockIdx.x * 256 + threadIdx.x;
    const int b = idx >> 10;
    const int d = idx & (DD - 1);
    float m = -INFINITY;
    #pragma unroll
    for (int t = 0; t < TT; t++) {
        if (inds[b * TT + t] != 0)
            m = fmaxf(m, y_word[(long)(b * TT + t) * DD + d]);
    }
    y_pool[idx] = m;
}

__global__ void softmax_out(const float* __restrict__ w_raw,
                            const float* __restrict__ y_word,
                            float* __restrict__ out)
{
    __shared__ float p[TT];
    const int b = blockIdx.x;
    if (threadIdx.x == 0) {
        float v[TT]; float mx = -INFINITY;
        #pragma unroll
        for (int t = 0; t < TT; t++) { v[t] = w_raw[b * TT + t]; mx = fmaxf(mx, v[t]); }
        float s = 0.f;
        #pragma unroll
        for (int t = 0; t < TT; t++) { v[t] = expf(v[t] - mx); s += v[t]; }
        const float inv = 1.f / s;
        #pragma unroll
        for (int t = 0; t < TT; t++) p[t] = v[t] * inv;
    }
    __syncthreads();
    for (int d = threadIdx.x; d < DD; d += 256) {
        float s = 0.f;
        #pragma unroll
        for (int t = 0; t < TT; t++)
            s += p[t] * y_word[((long)(b * TT + t)) * DD + d];
        out[(long)b * DD + d] = s;
    }
}

// ---------------- host launch --------------------------------------------------
extern "C" void kernel_launch(void* const* d_in, const int* in_sizes, int n_in,
                              void* d_out, int out_size)
{
    const int*   inds     = (const int*)  d_in[0];
    const float* emb      = (const float*)d_in[1];
    const float* w_ih_f   = (const float*)d_in[2];
    const float* w_hh_f   = (const float*)d_in[3];
    const float* b_ih_f   = (const float*)d_in[4];
    const float* b_hh_f   = (const float*)d_in[5];
    const float* w_ih_b   = (const float*)d_in[6];
    const float* w_hh_b   = (const float*)d_in[7];
    const float* b_ih_b   = (const float*)d_in[8];
    const float* b_hh_b   = (const float*)d_in[9];
    const float* w_local  = (const float*)d_in[10];
    const float* b_local  = (const float*)d_in[11];
    const float* w_global = (const float*)d_in[12];
    const float* b_global = (const float*)d_in[13];
    const float* w_common = (const float*)d_in[14];
    const float* b_common = (const float*)d_in[15];
    float* out = (float*)d_out;

    float *git_f, *git_b, *yw, *yp, *gw, *wraw;
    uint32_t *whht, *wlt, *htf;
    cudaGetSymbolAddress((void**)&git_f, g_git_f);
    cudaGetSymbolAddress((void**)&git_b, g_git_b);
    cudaGetSymbolAddress((void**)&whht, g_whht);
    cudaGetSymbolAddress((void**)&wlt,  g_wlt);
    cudaGetSymbolAddress((void**)&htf,  g_htf);
    cudaGetSymbolAddress((void**)&yw,   g_yword);
    cudaGetSymbolAddress((void**)&yp,   g_ypool);
    cudaGetSymbolAddress((void**)&gw,   g_gw);
    cudaGetSymbolAddress((void**)&wraw, g_wraw);

    cudaFuncSetAttribute(tgemm,    cudaFuncAttributeMaxDynamicSharedMemorySize, SMEM_B);
    cudaFuncSetAttribute(attn_w,   cudaFuncAttributeMaxDynamicSharedMemorySize, SMEM_B);
    cudaFuncSetAttribute(rec_step, cudaFuncAttributeMaxDynamicSharedMemorySize, R_SMEM);

    // 0. weight prep (permuted tf32)
    prep_whh<<<(2 * G3 * HID) / 256, 256>>>(w_hh_f, w_hh_b, whht);
    prep_wl<<<(DD * DD) / 256, 256>>>(w_local, wlt);

    // 1. zero hidden-state tf32 buffers
    zero_htf<<<(2 * 2 * BH) / 256, 256>>>(htf);

    // 2. per-vocab gi table (incl. b_ih), both dirs
    dim3 gt_grid((VOCAB + 127) / 128, G3 / 128, 2);
    tgemm<<<gt_grid, 256, SMEM_B>>>(emb, emb, EMBD,
                                    w_ih_f, w_ih_b, b_ih_f, b_ih_b, nullptr,
                                    git_f, git_b, VOCAB, G3, EMBD, 0);

    // 3. fused bidirectional GRU recurrence
    dim3 rec_grid(BATCH / 64, HID / 128, 2);
    for (int t = 0; t < TT; t++) {
        rec_step<<<rec_grid, 256, R_SMEM>>>(inds, git_f, git_b, whht,
                                            b_hh_f, b_hh_b, htf, yw, t);
    }

    // 4. masked max pool
    maxpool<<<(BATCH * DD) / 256, 256>>>(inds, yw, yp);

    // 5. gw = tanh(y_pool @ w_global^T + b_global) * w_common
    dim3 gw_grid(BATCH / 128, DD / 128, 1);
    tgemm<<<gw_grid, 256, SMEM_B>>>(yp, yp, DD,
                                    w_global, w_global, b_global, b_global, w_common,
                                    gw, gw, BATCH, DD, DD, 1);

    // 6. fused l_emb -> tanh -> dot(gw) -> attention logits
    attn_w<<<BT / 128, 256, SMEM_B>>>(yw, wlt, b_local, gw, b_common, wraw);

    // 7. softmax over T + weighted sum
    softmax_out<<<BATCH, 256>>>(wraw, yw, out);
}

// round 7
// speedup vs baseline: 1.0848x; 1.0848x over previous
#include <cuda_runtime.h>
#include <math.h>
#include <stdint.h>

#define BATCH 4096
#define TT    15
#define EMBD  300
#define HID   512
#define G3    1536
#define DD    1024
#define BT    (BATCH*TT)
#define VOCAB 12000
#define BH    (BATCH*HID)

#define SROW      36                 // smem row stride in u32 (32 + 4 pad)
#define STAGE_U32 (128*SROW)
#define SMEM_B    (2*2*STAGE_U32*4)  // tgemm/attn_w smem: 73728 B

// fused recurrence: A(64 rows) + B(192 rows) per stage, 3 stages (cp.async ring)
#define R_A_U32   (64*SROW)          // 2304
#define R_B_U32   (192*SROW)         // 6912
#define R_STAGE   (R_A_U32 + R_B_U32)  // 9216 u32
#define R_STAGES  3
#define R_SMEM    (R_STAGES*R_STAGE*4) // 110592 B  (2 CTAs/SM fit in 227KB)

// ---------------- scratch -----------------------------------------------------
__device__ float    g_git_f[(size_t)VOCAB * G3];     // gi table fwd (incl b_ih)
__device__ float    g_git_b[(size_t)VOCAB * G3];
__device__ uint32_t g_whht[(size_t)2 * 16 * G3 * 32]; // pre-permuted tf32 w_hh
__device__ uint32_t g_wlt [(size_t)32 * DD * 32];     // pre-permuted tf32 w_local
__device__ uint32_t g_htf [(size_t)2 * 2 * BH];       // permuted tf32 h, [dir][buf]
__device__ float    g_yword[(size_t)BT * DD];
__device__ float    g_ypool[BATCH * DD];
__device__ float    g_gw  [BATCH * DD];
__device__ float    g_wraw[BT];

// ---------------- TF32 helpers -------------------------------------------------
__device__ __forceinline__ uint32_t f2tf(float x) {
    uint32_t r; asm("cvt.rna.tf32.f32 %0, %1;" : "=r"(r) : "f"(x)); return r;
}
__device__ __forceinline__ void mma8(float* c,
    uint32_t a0, uint32_t a1, uint32_t a2, uint32_t a3,
    uint32_t b0, uint32_t b1)
{
    asm volatile(
        "mma.sync.aligned.m16n8k8.row.col.f32.tf32.tf32.f32 "
        "{%0,%1,%2,%3},{%4,%5,%6,%7},{%8,%9},{%0,%1,%2,%3};"
        : "+f"(c[0]), "+f"(c[1]), "+f"(c[2]), "+f"(c[3])
        : "r"(a0), "r"(a1), "r"(a2), "r"(a3), "r"(b0), "r"(b1));
}
__device__ __forceinline__ float sigm(float x) { return 1.f / (1.f + expf(-x)); }
__device__ __forceinline__ void cp16(uint32_t saddr, const void* g) {
    asm volatile("cp.async.cg.shared.global [%0], [%1], 16;" :: "r"(saddr), "l"(g));
}

// ---------------- weight prep (one-time, permuted tf32) ------------------------
// slot p(c) = (c%4)*8 + c/4 within each 32-wide k-chunk
__global__ void prep_whh(const float* __restrict__ wf, const float* __restrict__ wb,
                         uint32_t* __restrict__ out)
{
    const int idx = blockIdx.x * 256 + threadIdx.x;      // 2*1536*512
    const int per = G3 * HID;
    const int dir = idx / per, rem = idx % per;
    const int row = rem >> 9, k = rem & 511;
    const int kc = k >> 5, c = k & 31;
    const int p = (c & 3) * 8 + (c >> 2);
    const float* W = dir ? wb : wf;
    out[(((size_t)dir * 16 + kc) * G3 + row) * 32 + p] = f2tf(W[(size_t)row * HID + k]);
}
__global__ void prep_wl(const float* __restrict__ wl, uint32_t* __restrict__ out)
{
    const int idx = blockIdx.x * 256 + threadIdx.x;      // 1024*1024
    const int row = idx >> 10, k = idx & 1023;
    const int kc = k >> 5, c = k & 31;
    const int p = (c & 3) * 8 + (c >> 2);
    out[((size_t)kc * DD + row) * 32 + p] = f2tf(wl[idx]);
}

// ================= generic 128x128 TF32 GEMM (git + gw) ========================
__device__ __forceinline__ void stage_load(
    const float* const* aptr, const float* const* wptr,
    int k, int K, float4* ra, float4* rb)
{
    const float4 z4 = make_float4(0.f, 0.f, 0.f, 0.f);
    const bool v = (k < K);
    #pragma unroll
    for (int i = 0; i < 4; i++) {
        ra[i] = v ? *(const float4*)(aptr[i] + k) : z4;
        rb[i] = v ? *(const float4*)(wptr[i] + k) : z4;
    }
}
__device__ __forceinline__ void stage_store(
    uint32_t* dst, int lr, int lc4, const float4* ra, const float4* rb)
{
    uint32_t* db = dst + STAGE_U32;
    #pragma unroll
    for (int i = 0; i < 4; i++) {
        const int base = (lr + i * 32) * SROW + lc4;
        dst[base +  0] = f2tf(ra[i].x);
        dst[base +  8] = f2tf(ra[i].y);
        dst[base + 16] = f2tf(ra[i].z);
        dst[base + 24] = f2tf(ra[i].w);
        db [base +  0] = f2tf(rb[i].x);
        db [base +  8] = f2tf(rb[i].y);
        db [base + 16] = f2tf(rb[i].z);
        db [base + 24] = f2tf(rb[i].w);
    }
}
__device__ __forceinline__ void mm_tile(
    const uint32_t* As, const uint32_t* Bs,
    int wm0, int wn0, int g, int q, float (*c)[8][4])
{
    const uint4* As4 = (const uint4*)As;
    const uint4* Bs4 = (const uint4*)Bs;
    #pragma unroll
    for (int h = 0; h < 2; h++) {
        const int fo = q * 2 + h;
        const uint4 aL0 = As4[(wm0 + g     ) * 9 + fo];
        const uint4 aH0 = As4[(wm0 + g +  8) * 9 + fo];
        const uint4 aL1 = As4[(wm0 + g + 16) * 9 + fo];
        const uint4 aH1 = As4[(wm0 + g + 24) * 9 + fo];
        uint4 bf[8];
        #pragma unroll
        for (int nt = 0; nt < 8; nt++)
            bf[nt] = Bs4[(wn0 + nt * 8 + g) * 9 + fo];
        #pragma unroll
        for (int s = 0; s < 2; s++) {
            const uint32_t A00 = s ? aL0.z : aL0.x;
            const uint32_t A20 = s ? aL0.w : aL0.y;
            const uint32_t A10 = s ? aH0.z : aH0.x;
            const uint32_t A30 = s ? aH0.w : aH0.y;
            const uint32_t A01 = s ? aL1.z : aL1.x;
            const uint32_t A21 = s ? aL1.w : aL1.y;
            const uint32_t A11 = s ? aH1.z : aH1.x;
            const uint32_t A31 = s ? aH1.w : aH1.y;
            #pragma unroll
            for (int nt = 0; nt < 8; nt++) {
                const uint32_t B0 = s ? bf[nt].z : bf[nt].x;
                const uint32_t B1 = s ? bf[nt].w : bf[nt].y;
                mma8(c[0][nt], A00, A10, A20, A30, B0, B1);
                mma8(c[1][nt], A01, A11, A21, A31, B0, B1);
            }
        }
    }
}

__global__ void __launch_bounds__(256, 2) tgemm(
    const float* __restrict__ A,  const float* __restrict__ A2, int lda,
    const float* __restrict__ W,  const float* __restrict__ W2,
    const float* __restrict__ bias, const float* __restrict__ bias2,
    const float* __restrict__ wc,
    float* __restrict__ C, float* __restrict__ C2,
    int M, int N, int K, int epi)
{
    if (blockIdx.z == 1) { A = A2; W = W2; bias = bias2; C = C2; }
    extern __shared__ uint32_t sm[];

    const int tid  = threadIdx.x;
    const int lane = tid & 31, wid = tid >> 5;
    const int g = lane >> 2, q = lane & 3;
    const int wm0 = (wid & 3) * 32;
    const int wn0 = (wid >> 2) * 64;
    const int row0 = blockIdx.x * 128;
    const int col0 = blockIdx.y * 128;
    const int lr  = tid >> 3;
    const int lc4 = tid & 7;

    const float* aptr[4];
    const float* wptr[4];
    #pragma unroll
    for (int i = 0; i < 4; i++) {
        int ar = row0 + lr + i * 32;
        if (ar >= M) ar = M - 1;
        aptr[i] = A + (long)ar * lda;
        wptr[i] = W + (long)(col0 + lr + i * 32) * K;
    }

    float c[2][8][4];
    #pragma unroll
    for (int mt = 0; mt < 2; mt++)
        #pragma unroll
        for (int nt = 0; nt < 8; nt++)
            #pragma unroll
            for (int j = 0; j < 4; j++) c[mt][nt][j] = 0.f;

    float4 ra[4], rb[4];
    const int nk = (K + 31) / 32;

    stage_load(aptr, wptr, lc4 * 4, K, ra, rb);
    stage_store(sm, lr, lc4, ra, rb);
    __syncthreads();

    for (int it = 0; it < nk; it++) {
        const bool more = (it + 1 < nk);
        if (more) stage_load(aptr, wptr, (it + 1) * 32 + lc4 * 4, K, ra, rb);
        const uint32_t* cur = sm + (it & 1) * (2 * STAGE_U32);
        mm_tile(cur, cur + STAGE_U32, wm0, wn0, g, q, c);
        if (more) {
            stage_store(sm + ((it + 1) & 1) * (2 * STAGE_U32), lr, lc4, ra, rb);
            __syncthreads();
        }
    }

    #pragma unroll
    for (int mt = 0; mt < 2; mt++) {
        const int r = row0 + wm0 + mt * 16 + g;
        #pragma unroll
        for (int nt = 0; nt < 8; nt++) {
            const int n = col0 + wn0 + nt * 8 + q * 2;
            const float b0 = bias[n], b1 = bias[n + 1];
            float v00 = c[mt][nt][0] + b0, v01 = c[mt][nt][1] + b1;
            float v10 = c[mt][nt][2] + b0, v11 = c[mt][nt][3] + b1;
            if (epi == 1) {
                const float w0 = wc[n], w1 = wc[n + 1];
                v00 = tanhf(v00) * w0; v01 = tanhf(v01) * w1;
                v10 = tanhf(v10) * w0; v11 = tanhf(v11) * w1;
            }
            if (r < M)
                *(float2*)(C + (long)r * N + n) = make_float2(v00, v01);
            if (r + 8 < M)
                *(float2*)(C + (long)(r + 8) * N + n) = make_float2(v10, v11);
        }
    }
}

// ================= fused GRU recurrence step (2 CTAs/SM) =======================
// CTA: 64 batch x 64 hidden, 3 gates (192 accum cols). A = h_tf, B = g_whht.
__global__ void __launch_bounds__(256, 2) rec_step(
    const int* __restrict__ inds,
    const float* __restrict__ git_f, const float* __restrict__ git_b,
    const uint32_t* __restrict__ whht,
    const float* __restrict__ bhh_f, const float* __restrict__ bhh_b,
    uint32_t* __restrict__ htf,
    float* __restrict__ y_word, int t)
{
    const int dir = blockIdx.z;
    const int cur = t & 1, nxt = cur ^ 1;
    const float* git = dir ? git_b : git_f;
    const float* bhh = dir ? bhh_b : bhh_f;
    const int tt  = dir ? (TT - 1 - t) : t;
    const int off = dir ? HID : 0;
    const uint32_t* Wp    = whht + (size_t)dir * 16 * G3 * 32;
    const uint32_t* hprev = htf + ((size_t)dir * 2 + cur) * BH;
    uint32_t*       hnext = htf + ((size_t)dir * 2 + nxt) * BH;

    extern __shared__ uint32_t sm[];
    const uint32_t sbase = (uint32_t)__cvta_generic_to_shared(sm);

    const int tid  = threadIdx.x;
    const int lane = tid & 31, wid = tid >> 5;
    const int g = lane >> 2, q = lane & 3;
    const int wm0 = (wid & 1) * 32;       // 2 m-warps (32 rows each)
    const int wn0 = (wid >> 1) * 16;      // 4 n-warps (16 hid cols each)
    const int row0 = blockIdx.x * 64;     // batch tile
    const int col0 = blockIdx.y * 64;     // hidden tile

    // cp.async issue for one k-chunk kc into stage st (8 cp16 per thread)
    auto issue = [&](int kc, int st) {
        const uint32_t s0 = sbase + st * R_STAGE * 4;
        // A: 64 rows x 8 units
        #pragma unroll
        for (int s = 0; s < 2; s++) {
            const int u = tid + s * 256;
            const int r = u >> 3, j = u & 7;
            cp16(s0 + (r * SROW + j * 4) * 4,
                 hprev + (size_t)(row0 + r) * HID + kc * 32 + j * 4);
        }
        // B: 192 rows (3 gates x 64 hid) x 8 units
        #pragma unroll
        for (int s = 0; s < 6; s++) {
            const int u = tid + s * 256;
            const int r = u >> 3, j = u & 7;           // r: 0..191
            const int gate = r >> 6, wi = r & 63;
            cp16(s0 + (R_A_U32 + r * SROW + j * 4) * 4,
                 Wp + ((size_t)kc * G3 + gate * HID + col0 + wi) * 32 + j * 4);
        }
        asm volatile("cp.async.commit_group;");
    };

    float c[3][2][2][4];
    #pragma unroll
    for (int gt = 0; gt < 3; gt++)
        #pragma unroll
        for (int mt = 0; mt < 2; mt++)
            #pragma unroll
            for (int nt = 0; nt < 2; nt++)
                #pragma unroll
                for (int j = 0; j < 4; j++) c[gt][mt][nt][j] = 0.f;

    const int nk = HID / 32;  // 16
    issue(0, 0);
    issue(1, 1);

    for (int it = 0; it < nk; it++) {
        if (it + 1 < nk) asm volatile("cp.async.wait_group 1;");
        else             asm volatile("cp.async.wait_group 0;");
        __syncthreads();
        if (it + 2 < nk) issue(it + 2, (it + 2) % R_STAGES);

        const uint32_t* curS = sm + (it % R_STAGES) * R_STAGE;
        const uint4* As4 = (const uint4*)curS;
        const uint4* Bs4 = (const uint4*)(curS + R_A_U32);
        #pragma unroll
        for (int h = 0; h < 2; h++) {
            const int fo = q * 2 + h;
            const uint4 aL0 = As4[(wm0 + g     ) * 9 + fo];
            const uint4 aH0 = As4[(wm0 + g +  8) * 9 + fo];
            const uint4 aL1 = As4[(wm0 + g + 16) * 9 + fo];
            const uint4 aH1 = As4[(wm0 + g + 24) * 9 + fo];
            uint4 bf[3][2];
            #pragma unroll
            for (int gt = 0; gt < 3; gt++)
                #pragma unroll
                for (int nt = 0; nt < 2; nt++)
                    bf[gt][nt] = Bs4[(gt * 64 + wn0 + nt * 8 + g) * 9 + fo];
            #pragma unroll
            for (int s = 0; s < 2; s++) {
                const uint32_t A00 = s ? aL0.z : aL0.x;
                const uint32_t A20 = s ? aL0.w : aL0.y;
                const uint32_t A10 = s ? aH0.z : aH0.x;
                const uint32_t A30 = s ? aH0.w : aH0.y;
                const uint32_t A01 = s ? aL1.z : aL1.x;
                const uint32_t A21 = s ? aL1.w : aL1.y;
                const uint32_t A11 = s ? aH1.z : aH1.x;
                const uint32_t A31 = s ? aH1.w : aH1.y;
                #pragma unroll
                for (int gt = 0; gt < 3; gt++)
                    #pragma unroll
                    for (int nt = 0; nt < 2; nt++) {
                        const uint32_t B0 = s ? bf[gt][nt].z : bf[gt][nt].x;
                        const uint32_t B1 = s ? bf[gt][nt].w : bf[gt][nt].y;
                        mma8(c[gt][0][nt], A00, A10, A20, A30, B0, B1);
                        mma8(c[gt][1][nt], A01, A11, A21, A31, B0, B1);
                    }
            }
        }
    }

    // ---- GRU cell epilogue ----
    #pragma unroll
    for (int mt = 0; mt < 2; mt++) {
        #pragma unroll
        for (int rr = 0; rr < 2; rr++) {
            const int b = row0 + wm0 + mt * 16 + g + rr * 8;
            const int tok = inds[b * TT + tt];
            const float* gib = git + (long)tok * G3;
            #pragma unroll
            for (int nt = 0; nt < 2; nt++) {
                const int hg = col0 + wn0 + nt * 8 + q * 2;
                const int j0 = rr * 2;
                #pragma unroll
                for (int e = 0; e < 2; e++) {
                    const int hh = hg + e;
                    const int cc = hh & 31;
                    const long off_tf = (long)b * HID + (hh >> 5) * 32
                                      + (cc & 3) * 8 + (cc >> 2);
                    const float gir = gib[hh];
                    const float giz = gib[HID + hh];
                    const float gin = gib[2 * HID + hh];
                    const float ghr = c[0][mt][nt][j0 + e] + bhh[hh];
                    const float ghz = c[1][mt][nt][j0 + e] + bhh[HID + hh];
                    const float ghn = c[2][mt][nt][j0 + e] + bhh[2 * HID + hh];
                    const float hp = __uint_as_float(hprev[off_tf]);
                    const float r = sigm(gir + ghr);
                    const float z = sigm(giz + ghz);
                    const float n = tanhf(gin + r * ghn);
                    const float hnew = (1.f - z) * n + z * hp;
                    hnext[off_tf] = f2tf(hnew);
                    y_word[(long)(b * TT + tt) * DD + off + hh] = hnew;
                }
            }
        }
    }
}

// ---------------- fused attention logits (B from pre-permuted w_local) ---------
__global__ void __launch_bounds__(256, 2) attn_w(
    const float* __restrict__ yw, const uint32_t* __restrict__ wlt,
    const float* __restrict__ bl, const float* __restrict__ gw,
    const float* __restrict__ bc, float* __restrict__ wraw)
{
    extern __shared__ uint32_t sm[];
    __shared__ float red[128][9];

    const int tid  = threadIdx.x;
    const int lane = tid & 31, wid = tid >> 5;
    const int g = lane >> 2, q = lane & 3;
    const int wm0 = (wid & 3) * 32;
    const int wn0 = (wid >> 2) * 64;
    const int row0 = blockIdx.x * 128;
    const int lr  = tid >> 3;
    const int lc4 = tid & 7;

    const float* aptr[4];
    #pragma unroll
    for (int i = 0; i < 4; i++)
        aptr[i] = yw + (long)(row0 + lr + i * 32) * DD;

    int rbi0[2], rbi1[2];
    #pragma unroll
    for (int mt = 0; mt < 2; mt++) {
        const int r = row0 + wm0 + mt * 16 + g;
        rbi0[mt] = r / TT;
        rbi1[mt] = (r + 8) / TT;
    }
    float rowsum[2][2] = {{0.f, 0.f}, {0.f, 0.f}};

    const int nk = DD / 32;

    for (int ct = 0; ct < DD / 128; ct++) {
        const int col0 = ct * 128;

        float c[2][8][4];
        #pragma unroll
        for (int mt = 0; mt < 2; mt++)
            #pragma unroll
            for (int nt = 0; nt < 8; nt++)
                #pragma unroll
                for (int j = 0; j < 4; j++) c[mt][nt][j] = 0.f;

        float4 ra[4];
        uint4  rbu[4];
        #pragma unroll
        for (int i = 0; i < 4; i++) {
            ra[i]  = *(const float4*)(aptr[i] + lc4 * 4);
            rbu[i] = *(const uint4*)(wlt + ((size_t)0 * DD + col0 + lr + i * 32) * 32 + lc4 * 4);
        }
        {
            uint32_t* sa = sm;
            uint32_t* sb = sm + STAGE_U32;
            #pragma unroll
            for (int i = 0; i < 4; i++) {
                const int base = (lr + i * 32) * SROW + lc4;
                sa[base+0]=f2tf(ra[i].x); sa[base+8]=f2tf(ra[i].y);
                sa[base+16]=f2tf(ra[i].z); sa[base+24]=f2tf(ra[i].w);
                *(uint4*)&sb[(lr + i * 32) * SROW + lc4 * 4] = rbu[i];
            }
        }
        __syncthreads();

        for (int it = 0; it < nk; it++) {
            const bool more = (it + 1 < nk);
            if (more) {
                const int k = (it + 1) * 32 + lc4 * 4;
                #pragma unroll
                for (int i = 0; i < 4; i++) {
                    ra[i]  = *(const float4*)(aptr[i] + k);
                    rbu[i] = *(const uint4*)(wlt + ((size_t)(it + 1) * DD + col0 + lr + i * 32) * 32 + lc4 * 4);
                }
            }
            const uint32_t* curS = sm + (it & 1) * (2 * STAGE_U32);
            mm_tile(curS, curS + STAGE_U32, wm0, wn0, g, q, c);
            if (more) {
                uint32_t* nx = sm + ((it + 1) & 1) * (2 * STAGE_U32);
                uint32_t* sa = nx;
                uint32_t* sb = nx + STAGE_U32;
                #pragma unroll
                for (int i = 0; i < 4; i++) {
                    const int base = (lr + i * 32) * SROW + lc4;
                    sa[base+0]=f2tf(ra[i].x); sa[base+8]=f2tf(ra[i].y);
                    sa[base+16]=f2tf(ra[i].z); sa[base+24]=f2tf(ra[i].w);
                    *(uint4*)&sb[(lr + i * 32) * SROW + lc4 * 4] = rbu[i];
                }
                __syncthreads();
            }
        }

        #pragma unroll
        for (int mt = 0; mt < 2; mt++) {
            #pragma unroll
            for (int nt = 0; nt < 8; nt++) {
                const int n = col0 + wn0 + nt * 8 + q * 2;
                const float bb0 = bl[n], bb1 = bl[n + 1];
                rowsum[mt][0] += tanhf(c[mt][nt][0] + bb0) * gw[(long)rbi0[mt] * DD + n]
                               + tanhf(c[mt][nt][1] + bb1) * gw[(long)rbi0[mt] * DD + n + 1];
                rowsum[mt][1] += tanhf(c[mt][nt][2] + bb0) * gw[(long)rbi1[mt] * DD + n]
                               + tanhf(c[mt][nt][3] + bb1) * gw[(long)rbi1[mt] * DD + n + 1];
            }
        }
        __syncthreads();
    }

    const int rc = (wid >> 2) * 4 + q;
    #pragma unroll
    for (int mt = 0; mt < 2; mt++) {
        red[wm0 + mt * 16 + g    ][rc] = rowsum[mt][0];
        red[wm0 + mt * 16 + g + 8][rc] = rowsum[mt][1];
    }
    __syncthreads();
    if (tid < 128) {
        float s = 0.f;
        #pragma unroll
        for (int x = 0; x < 8; x++) s += red[tid][x];
        wraw[row0 + tid] = s + bc[0];
    }
}

// ---------------- small kernels ------------------------------------------------
__global__ void zero_htf(uint32_t* __restrict__ htf)
{
    const size_t i = (size_t)blockIdx.x * 256 + threadIdx.x;
    htf[i] = 0u;
}

__global__ void maxpool(const int* __restrict__ inds,
                        const float* __restrict__ y_word,
                        float* __restrict__ y_pool)
{
    const int idx = blockIdx.x * 256 + threadIdx.x;
    const int b = idx >> 10;
    const int d = idx & (DD - 1);
    float m = -INFINITY;
    #pragma unroll
    for (int t = 0; t < TT; t++) {
        if (inds[b * TT + t] != 0)
            m = fmaxf(m, y_word[(long)(b * TT + t) * DD + d]);
    }
    y_pool[idx] = m;
}

__global__ void softmax_out(const float* __restrict__ w_raw,
                            const float* __restrict__ y_word,
                            float* __restrict__ out)
{
    __shared__ float p[TT];
    const int b = blockIdx.x;
    if (threadIdx.x == 0) {
        float v[TT]; float mx = -INFINITY;
        #pragma unroll
        for (int t = 0; t < TT; t++) { v[t] = w_raw[b * TT + t]; mx = fmaxf(mx, v[t]); }
        float s = 0.f;
        #pragma unroll
        for (int t = 0; t < TT; t++) { v[t] = expf(v[t] - mx); s += v[t]; }
        const float inv = 1.f / s;
        #pragma unroll
        for (int t = 0; t < TT; t++) p[t] = v[t] * inv;
    }
    __syncthreads();
    for (int d = threadIdx.x; d < DD; d += 256) {
        float s = 0.f;
        #pragma unroll
        for (int t = 0; t < TT; t++)
            s += p[t] * y_word[((long)(b * TT + t)) * DD + d];
        out[(long)b * DD + d] = s;
    }
}

// ---------------- host launch --------------------------------------------------
extern "C" void kernel_launch(void* const* d_in, const int* in_sizes, int n_in,
                              void* d_out, int out_size)
{
    const int*   inds     = (const int*)  d_in[0];
    const float* emb      = (const float*)d_in[1];
    const float* w_ih_f   = (const float*)d_in[2];
    const float* w_hh_f   = (const float*)d_in[3];
    const float* b_ih_f   = (const float*)d_in[4];
    const float* b_hh_f   = (const float*)d_in[5];
    const float* w_ih_b   = (const float*)d_in[6];
    const float* w_hh_b   = (const float*)d_in[7];
    const float* b_ih_b   = (const float*)d_in[8];
    const float* b_hh_b   = (const float*)d_in[9];
    const float* w_local  = (const float*)d_in[10];
    const float* b_local  = (const float*)d_in[11];
    const float* w_global = (const float*)d_in[12];
    const float* b_global = (const float*)d_in[13];
    const float* w_common = (const float*)d_in[14];
    const float* b_common = (const float*)d_in[15];
    float* out = (float*)d_out;

    float *git_f, *git_b, *yw, *yp, *gw, *wraw;
    uint32_t *whht, *wlt, *htf;
    cudaGetSymbolAddress((void**)&git_f, g_git_f);
    cudaGetSymbolAddress((void**)&git_b, g_git_b);
    cudaGetSymbolAddress((void**)&whht, g_whht);
    cudaGetSymbolAddress((void**)&wlt,  g_wlt);
    cudaGetSymbolAddress((void**)&htf,  g_htf);
    cudaGetSymbolAddress((void**)&yw,   g_yword);
    cudaGetSymbolAddress((void**)&yp,   g_ypool);
    cudaGetSymbolAddress((void**)&gw,   g_gw);
    cudaGetSymbolAddress((void**)&wraw, g_wraw);

    cudaFuncSetAttribute(tgemm,    cudaFuncAttributeMaxDynamicSharedMemorySize, SMEM_B);
    cudaFuncSetAttribute(attn_w,   cudaFuncAttributeMaxDynamicSharedMemorySize, SMEM_B);
    cudaFuncSetAttribute(rec_step, cudaFuncAttributeMaxDynamicSharedMemorySize, R_SMEM);

    // 0. weight prep (permuted tf32)
    prep_whh<<<(2 * G3 * HID) / 256, 256>>>(w_hh_f, w_hh_b, whht);
    prep_wl<<<(DD * DD) / 256, 256>>>(w_local, wlt);

    // 1. zero hidden-state tf32 buffers
    zero_htf<<<(2 * 2 * BH) / 256, 256>>>(htf);

    // 2. per-vocab gi table (incl. b_ih), both dirs
    dim3 gt_grid((VOCAB + 127) / 128, G3 / 128, 2);
    tgemm<<<gt_grid, 256, SMEM_B>>>(emb, emb, EMBD,
                                    w_ih_f, w_ih_b, b_ih_f, b_ih_b, nullptr,
                                    git_f, git_b, VOCAB, G3, EMBD, 0);

    // 3. fused bidirectional GRU recurrence (64x64 tiles, 2 CTAs/SM)
    dim3 rec_grid(BATCH / 64, HID / 64, 2);
    for (int t = 0; t < TT; t++) {
        rec_step<<<rec_grid, 256, R_SMEM>>>(inds, git_f, git_b, whht,
                                            b_hh_f, b_hh_b, htf, yw, t);
    }

    // 4. masked max pool
    maxpool<<<(BATCH * DD) / 256, 256>>>(inds, yw, yp);

    // 5. gw = tanh(y_pool @ w_global^T + b_global) * w_common
    dim3 gw_grid(BATCH / 128, DD / 128, 1);
    tgemm<<<gw_grid, 256, SMEM_B>>>(yp, yp, DD,
                                    w_global, w_global, b_global, b_global, w_common,
                                    gw, gw, BATCH, DD, DD, 1);

    // 6. fused l_emb -> tanh -> dot(gw) -> attention logits
    attn_w<<<BT / 128, 256, SMEM_B>>>(yw, wlt, b_local, gw, b_common, wraw);

    // 7. softmax over T + weighted sum
    softmax_out<<<BATCH, 256>>>(wraw, yw, out);
}

// round 8
// speedup vs baseline: 1.1553x; 1.0650x over previous
#include <cuda_runtime.h>
#include <math.h>
#include <stdint.h>

#define BATCH 4096
#define TT    15
#define EMBD  300
#define HID   512
#define G3    1536
#define DD    1024
#define BT    (BATCH*TT)
#define VOCAB 12000
#define BH    (BATCH*HID)

#define SROW      36                 // smem row stride in u32 (32 + 4 pad)
#define STAGE_U32 (128*SROW)
#define SMEM_B    (2*2*STAGE_U32*4)  // tgemm smem: 73728 B

// fused recurrence: A(64 rows) + B(192 rows) per stage, 3 stages (cp.async ring)
#define R_A_U32   (64*SROW)
#define R_B_U32   (192*SROW)
#define R_STAGE   (R_A_U32 + R_B_U32)
#define R_STAGES  3
#define R_SMEM    (R_STAGES*R_STAGE*4) // 110592 B

// attn_w: A(128 rows) + B(256 rows) per stage, 2 stages
#define AT_A_U32  (128*SROW)           // 4608
#define AT_B_U32  (256*SROW)           // 9216
#define AT_STAGE  (AT_A_U32 + AT_B_U32)
#define AT_SMEM   (2*AT_STAGE*4)       // 110592 B

// ---------------- scratch -----------------------------------------------------
__device__ float    g_git_f[(size_t)VOCAB * G3];
__device__ float    g_git_b[(size_t)VOCAB * G3];
__device__ uint32_t g_whht[(size_t)2 * 16 * G3 * 32]; // pre-permuted tf32 w_hh
__device__ uint32_t g_wlt [(size_t)32 * DD * 32];     // pre-permuted tf32 w_local
__device__ uint32_t g_htf [(size_t)2 * 2 * BH];       // permuted tf32 h, [dir][buf]
__device__ float    g_yword[(size_t)BT * DD];
__device__ float    g_ypool[BATCH * DD];
__device__ float    g_gw  [BATCH * DD];
__device__ float    g_wraw[BT];

// ---------------- TF32 helpers -------------------------------------------------
__device__ __forceinline__ uint32_t f2tf(float x) {
    uint32_t r; asm("cvt.rna.tf32.f32 %0, %1;" : "=r"(r) : "f"(x)); return r;
}
__device__ __forceinline__ void mma8(float* c,
    uint32_t a0, uint32_t a1, uint32_t a2, uint32_t a3,
    uint32_t b0, uint32_t b1)
{
    asm volatile(
        "mma.sync.aligned.m16n8k8.row.col.f32.tf32.tf32.f32 "
        "{%0,%1,%2,%3},{%4,%5,%6,%7},{%8,%9},{%0,%1,%2,%3};"
        : "+f"(c[0]), "+f"(c[1]), "+f"(c[2]), "+f"(c[3])
        : "r"(a0), "r"(a1), "r"(a2), "r"(a3), "r"(b0), "r"(b1));
}
__device__ __forceinline__ float sigm(float x) { return 1.f / (1.f + expf(-x)); }
__device__ __forceinline__ void cp16(uint32_t saddr, const void* g) {
    asm volatile("cp.async.cg.shared.global [%0], [%1], 16;" :: "r"(saddr), "l"(g));
}

// ---------------- weight prep (one-time, permuted tf32) ------------------------
__global__ void prep_whh(const float* __restrict__ wf, const float* __restrict__ wb,
                         uint32_t* __restrict__ out)
{
    const int idx = blockIdx.x * 256 + threadIdx.x;
    const int per = G3 * HID;
    const int dir = idx / per, rem = idx % per;
    const int row = rem >> 9, k = rem & 511;
    const int kc = k >> 5, c = k & 31;
    const int p = (c & 3) * 8 + (c >> 2);
    const float* W = dir ? wb : wf;
    out[(((size_t)dir * 16 + kc) * G3 + row) * 32 + p] = f2tf(W[(size_t)row * HID + k]);
}
__global__ void prep_wl(const float* __restrict__ wl, uint32_t* __restrict__ out)
{
    const int idx = blockIdx.x * 256 + threadIdx.x;
    const int row = idx >> 10, k = idx & 1023;
    const int kc = k >> 5, c = k & 31;
    const int p = (c & 3) * 8 + (c >> 2);
    out[((size_t)kc * DD + row) * 32 + p] = f2tf(wl[idx]);
}

// ================= generic 128x128 TF32 GEMM (git + gw) ========================
__device__ __forceinline__ void stage_load(
    const float* const* aptr, const float* const* wptr,
    int k, int K, float4* ra, float4* rb)
{
    const float4 z4 = make_float4(0.f, 0.f, 0.f, 0.f);
    const bool v = (k < K);
    #pragma unroll
    for (int i = 0; i < 4; i++) {
        ra[i] = v ? *(const float4*)(aptr[i] + k) : z4;
        rb[i] = v ? *(const float4*)(wptr[i] + k) : z4;
    }
}
__device__ __forceinline__ void stage_store(
    uint32_t* dst, int lr, int lc4, const float4* ra, const float4* rb)
{
    uint32_t* db = dst + STAGE_U32;
    #pragma unroll
    for (int i = 0; i < 4; i++) {
        const int base = (lr + i * 32) * SROW + lc4;
        dst[base +  0] = f2tf(ra[i].x);
        dst[base +  8] = f2tf(ra[i].y);
        dst[base + 16] = f2tf(ra[i].z);
        dst[base + 24] = f2tf(ra[i].w);
        db [base +  0] = f2tf(rb[i].x);
        db [base +  8] = f2tf(rb[i].y);
        db [base + 16] = f2tf(rb[i].z);
        db [base + 24] = f2tf(rb[i].w);
    }
}
__device__ __forceinline__ void mm_tile(
    const uint32_t* As, const uint32_t* Bs,
    int wm0, int wn0, int g, int q, float (*c)[8][4])
{
    const uint4* As4 = (const uint4*)As;
    const uint4* Bs4 = (const uint4*)Bs;
    #pragma unroll
    for (int h = 0; h < 2; h++) {
        const int fo = q * 2 + h;
        const uint4 aL0 = As4[(wm0 + g     ) * 9 + fo];
        const uint4 aH0 = As4[(wm0 + g +  8) * 9 + fo];
        const uint4 aL1 = As4[(wm0 + g + 16) * 9 + fo];
        const uint4 aH1 = As4[(wm0 + g + 24) * 9 + fo];
        uint4 bf[8];
        #pragma unroll
        for (int nt = 0; nt < 8; nt++)
            bf[nt] = Bs4[(wn0 + nt * 8 + g) * 9 + fo];
        #pragma unroll
        for (int s = 0; s < 2; s++) {
            const uint32_t A00 = s ? aL0.z : aL0.x;
            const uint32_t A20 = s ? aL0.w : aL0.y;
            const uint32_t A10 = s ? aH0.z : aH0.x;
            const uint32_t A30 = s ? aH0.w : aH0.y;
            const uint32_t A01 = s ? aL1.z : aL1.x;
            const uint32_t A21 = s ? aL1.w : aL1.y;
            const uint32_t A11 = s ? aH1.z : aH1.x;
            const uint32_t A31 = s ? aH1.w : aH1.y;
            #pragma unroll
            for (int nt = 0; nt < 8; nt++) {
                const uint32_t B0 = s ? bf[nt].z : bf[nt].x;
                const uint32_t B1 = s ? bf[nt].w : bf[nt].y;
                mma8(c[0][nt], A00, A10, A20, A30, B0, B1);
                mma8(c[1][nt], A01, A11, A21, A31, B0, B1);
            }
        }
    }
}

__global__ void __launch_bounds__(256) tgemm(
    const float* __restrict__ A,  const float* __restrict__ A2, int lda,
    const float* __restrict__ W,  const float* __restrict__ W2,
    const float* __restrict__ bias, const float* __restrict__ bias2,
    const float* __restrict__ wc,
    float* __restrict__ C, float* __restrict__ C2,
    int M, int N, int K, int epi)
{
    if (blockIdx.z == 1) { A = A2; W = W2; bias = bias2; C = C2; }
    extern __shared__ uint32_t sm[];

    const int tid  = threadIdx.x;
    const int lane = tid & 31, wid = tid >> 5;
    const int g = lane >> 2, q = lane & 3;
    const int wm0 = (wid & 3) * 32;
    const int wn0 = (wid >> 2) * 64;
    const int row0 = blockIdx.x * 128;
    const int col0 = blockIdx.y * 128;
    const int lr  = tid >> 3;
    const int lc4 = tid & 7;

    const float* aptr[4];
    const float* wptr[4];
    #pragma unroll
    for (int i = 0; i < 4; i++) {
        int ar = row0 + lr + i * 32;
        if (ar >= M) ar = M - 1;
        aptr[i] = A + (long)ar * lda;
        wptr[i] = W + (long)(col0 + lr + i * 32) * K;
    }

    float c[2][8][4];
    #pragma unroll
    for (int mt = 0; mt < 2; mt++)
        #pragma unroll
        for (int nt = 0; nt < 8; nt++)
            #pragma unroll
            for (int j = 0; j < 4; j++) c[mt][nt][j] = 0.f;

    float4 ra[4], rb[4];
    const int nk = (K + 31) / 32;

    stage_load(aptr, wptr, lc4 * 4, K, ra, rb);
    stage_store(sm, lr, lc4, ra, rb);
    __syncthreads();

    for (int it = 0; it < nk; it++) {
        const bool more = (it + 1 < nk);
        if (more) stage_load(aptr, wptr, (it + 1) * 32 + lc4 * 4, K, ra, rb);
        const uint32_t* cur = sm + (it & 1) * (2 * STAGE_U32);
        mm_tile(cur, cur + STAGE_U32, wm0, wn0, g, q, c);
        if (more) {
            stage_store(sm + ((it + 1) & 1) * (2 * STAGE_U32), lr, lc4, ra, rb);
            __syncthreads();
        }
    }

    #pragma unroll
    for (int mt = 0; mt < 2; mt++) {
        const int r = row0 + wm0 + mt * 16 + g;
        #pragma unroll
        for (int nt = 0; nt < 8; nt++) {
            const int n = col0 + wn0 + nt * 8 + q * 2;
            const float b0 = bias[n], b1 = bias[n + 1];
            float v00 = c[mt][nt][0] + b0, v01 = c[mt][nt][1] + b1;
            float v10 = c[mt][nt][2] + b0, v11 = c[mt][nt][3] + b1;
            if (epi == 1) {
                const float w0 = wc[n], w1 = wc[n + 1];
                v00 = tanhf(v00) * w0; v01 = tanhf(v01) * w1;
                v10 = tanhf(v10) * w0; v11 = tanhf(v11) * w1;
            }
            if (r < M)
                *(float2*)(C + (long)r * N + n) = make_float2(v00, v01);
            if (r + 8 < M)
                *(float2*)(C + (long)(r + 8) * N + n) = make_float2(v10, v11);
        }
    }
}

// ================= fused GRU recurrence step (unchanged from R7) ===============
__global__ void __launch_bounds__(256, 2) rec_step(
    const int* __restrict__ inds,
    const float* __restrict__ git_f, const float* __restrict__ git_b,
    const uint32_t* __restrict__ whht,
    const float* __restrict__ bhh_f, const float* __restrict__ bhh_b,
    uint32_t* __restrict__ htf,
    float* __restrict__ y_word, int t)
{
    const int dir = blockIdx.z;
    const int cur = t & 1, nxt = cur ^ 1;
    const float* git = dir ? git_b : git_f;
    const float* bhh = dir ? bhh_b : bhh_f;
    const int tt  = dir ? (TT - 1 - t) : t;
    const int off = dir ? HID : 0;
    const uint32_t* Wp    = whht + (size_t)dir * 16 * G3 * 32;
    const uint32_t* hprev = htf + ((size_t)dir * 2 + cur) * BH;
    uint32_t*       hnext = htf + ((size_t)dir * 2 + nxt) * BH;

    extern __shared__ uint32_t sm[];
    const uint32_t sbase = (uint32_t)__cvta_generic_to_shared(sm);

    const int tid  = threadIdx.x;
    const int lane = tid & 31, wid = tid >> 5;
    const int g = lane >> 2, q = lane & 3;
    const int wm0 = (wid & 1) * 32;
    const int wn0 = (wid >> 1) * 16;
    const int row0 = blockIdx.x * 64;
    const int col0 = blockIdx.y * 64;

    auto issue = [&](int kc, int st) {
        const uint32_t s0 = sbase + st * R_STAGE * 4;
        #pragma unroll
        for (int s = 0; s < 2; s++) {
            const int u = tid + s * 256;
            const int r = u >> 3, j = u & 7;
            cp16(s0 + (r * SROW + j * 4) * 4,
                 hprev + (size_t)(row0 + r) * HID + kc * 32 + j * 4);
        }
        #pragma unroll
        for (int s = 0; s < 6; s++) {
            const int u = tid + s * 256;
            const int r = u >> 3, j = u & 7;
            const int gate = r >> 6, wi = r & 63;
            cp16(s0 + (R_A_U32 + r * SROW + j * 4) * 4,
                 Wp + ((size_t)kc * G3 + gate * HID + col0 + wi) * 32 + j * 4);
        }
        asm volatile("cp.async.commit_group;");
    };

    float c[3][2][2][4];
    #pragma unroll
    for (int gt = 0; gt < 3; gt++)
        #pragma unroll
        for (int mt = 0; mt < 2; mt++)
            #pragma unroll
            for (int nt = 0; nt < 2; nt++)
                #pragma unroll
                for (int j = 0; j < 4; j++) c[gt][mt][nt][j] = 0.f;

    const int nk = HID / 32;
    issue(0, 0);
    issue(1, 1);

    for (int it = 0; it < nk; it++) {
        if (it + 1 < nk) asm volatile("cp.async.wait_group 1;");
        else             asm volatile("cp.async.wait_group 0;");
        __syncthreads();
        if (it + 2 < nk) issue(it + 2, (it + 2) % R_STAGES);

        const uint32_t* curS = sm + (it % R_STAGES) * R_STAGE;
        const uint4* As4 = (const uint4*)curS;
        const uint4* Bs4 = (const uint4*)(curS + R_A_U32);
        #pragma unroll
        for (int h = 0; h < 2; h++) {
            const int fo = q * 2 + h;
            const uint4 aL0 = As4[(wm0 + g     ) * 9 + fo];
            const uint4 aH0 = As4[(wm0 + g +  8) * 9 + fo];
            const uint4 aL1 = As4[(wm0 + g + 16) * 9 + fo];
            const uint4 aH1 = As4[(wm0 + g + 24) * 9 + fo];
            uint4 bf[3][2];
            #pragma unroll
            for (int gt = 0; gt < 3; gt++)
                #pragma unroll
                for (int nt = 0; nt < 2; nt++)
                    bf[gt][nt] = Bs4[(gt * 64 + wn0 + nt * 8 + g) * 9 + fo];
            #pragma unroll
            for (int s = 0; s < 2; s++) {
                const uint32_t A00 = s ? aL0.z : aL0.x;
                const uint32_t A20 = s ? aL0.w : aL0.y;
                const uint32_t A10 = s ? aH0.z : aH0.x;
                const uint32_t A30 = s ? aH0.w : aH0.y;
                const uint32_t A01 = s ? aL1.z : aL1.x;
                const uint32_t A21 = s ? aL1.w : aL1.y;
                const uint32_t A11 = s ? aH1.z : aH1.x;
                const uint32_t A31 = s ? aH1.w : aH1.y;
                #pragma unroll
                for (int gt = 0; gt < 3; gt++)
                    #pragma unroll
                    for (int nt = 0; nt < 2; nt++) {
                        const uint32_t B0 = s ? bf[gt][nt].z : bf[gt][nt].x;
                        const uint32_t B1 = s ? bf[gt][nt].w : bf[gt][nt].y;
                        mma8(c[gt][0][nt], A00, A10, A20, A30, B0, B1);
                        mma8(c[gt][1][nt], A01, A11, A21, A31, B0, B1);
                    }
            }
        }
    }

    #pragma unroll
    for (int mt = 0; mt < 2; mt++) {
        #pragma unroll
        for (int rr = 0; rr < 2; rr++) {
            const int b = row0 + wm0 + mt * 16 + g + rr * 8;
            const int tok = inds[b * TT + tt];
            const float* gib = git + (long)tok * G3;
            #pragma unroll
            for (int nt = 0; nt < 2; nt++) {
                const int hg = col0 + wn0 + nt * 8 + q * 2;
                const int j0 = rr * 2;
                #pragma unroll
                for (int e = 0; e < 2; e++) {
                    const int hh = hg + e;
                    const int cc = hh & 31;
                    const long off_tf = (long)b * HID + (hh >> 5) * 32
                                      + (cc & 3) * 8 + (cc >> 2);
                    const float gir = gib[hh];
                    const float giz = gib[HID + hh];
                    const float gin = gib[2 * HID + hh];
                    const float ghr = c[0][mt][nt][j0 + e] + bhh[hh];
                    const float ghz = c[1][mt][nt][j0 + e] + bhh[HID + hh];
                    const float ghn = c[2][mt][nt][j0 + e] + bhh[2 * HID + hh];
                    const float hp = __uint_as_float(hprev[off_tf]);
                    const float r = sigm(gir + ghr);
                    const float z = sigm(giz + ghz);
                    const float n = tanhf(gin + r * ghn);
                    const float hnew = (1.f - z) * n + z * hp;
                    hnext[off_tf] = f2tf(hnew);
                    y_word[(long)(b * TT + tt) * DD + off + hh] = hnew;
                }
            }
        }
    }
}

// ---------------- fused attention logits: 512 threads, M=128 x N=256/pass ------
__global__ void __launch_bounds__(512) attn_w(
    const float* __restrict__ yw, const uint32_t* __restrict__ wlt,
    const float* __restrict__ bl, const float* __restrict__ gw,
    const float* __restrict__ bc, float* __restrict__ wraw)
{
    extern __shared__ uint32_t sm[];
    __shared__ float red[128][17];

    const int tid  = threadIdx.x;
    const int lane = tid & 31, wid = tid >> 5;       // wid 0..15
    const int g = lane >> 2, q = lane & 3;
    const int wm0 = (wid & 3) * 32;                  // 4 m-warps
    const int wn0 = (wid >> 2) * 64;                 // 4 n-warps
    const int row0 = blockIdx.x * 128;
    const int lr  = tid >> 3;                        // 0..63
    const int lc4 = tid & 7;

    const float* aptr[2];
    #pragma unroll
    for (int i = 0; i < 2; i++)
        aptr[i] = yw + (long)(row0 + lr + i * 64) * DD;

    int rbi0[2], rbi1[2];
    #pragma unroll
    for (int mt = 0; mt < 2; mt++) {
        const int r = row0 + wm0 + mt * 16 + g;
        rbi0[mt] = r / TT;
        rbi1[mt] = (r + 8) / TT;
    }
    float rowsum[2][2] = {{0.f, 0.f}, {0.f, 0.f}};

    const int nk = DD / 32;   // 32

    for (int ct = 0; ct < DD / 256; ct++) {          // 4 column passes
        const int col0 = ct * 256;

        float c[2][8][4];
        #pragma unroll
        for (int mt = 0; mt < 2; mt++)
            #pragma unroll
            for (int nt = 0; nt < 8; nt++)
                #pragma unroll
                for (int j = 0; j < 4; j++) c[mt][nt][j] = 0.f;

        float4 ra[2];
        uint4  rbu[4];
        #pragma unroll
        for (int i = 0; i < 2; i++)
            ra[i]  = *(const float4*)(aptr[i] + lc4 * 4);
        #pragma unroll
        for (int i = 0; i < 4; i++)
            rbu[i] = *(const uint4*)(wlt + ((size_t)0 * DD + col0 + lr + i * 64) * 32 + lc4 * 4);
        {
            uint32_t* sa = sm;
            uint32_t* sb = sm + AT_A_U32;
            #pragma unroll
            for (int i = 0; i < 2; i++) {
                const int base = (lr + i * 64) * SROW + lc4;
                sa[base+0]=f2tf(ra[i].x); sa[base+8]=f2tf(ra[i].y);
                sa[base+16]=f2tf(ra[i].z); sa[base+24]=f2tf(ra[i].w);
            }
            #pragma unroll
            for (int i = 0; i < 4; i++)
                *(uint4*)&sb[(lr + i * 64) * SROW + lc4 * 4] = rbu[i];
        }
        __syncthreads();

        for (int it = 0; it < nk; it++) {
            const bool more = (it + 1 < nk);
            if (more) {
                const int k = (it + 1) * 32 + lc4 * 4;
                #pragma unroll
                for (int i = 0; i < 2; i++)
                    ra[i]  = *(const float4*)(aptr[i] + k);
                #pragma unroll
                for (int i = 0; i < 4; i++)
                    rbu[i] = *(const uint4*)(wlt + ((size_t)(it + 1) * DD + col0 + lr + i * 64) * 32 + lc4 * 4);
            }
            const uint32_t* curS = sm + (it & 1) * AT_STAGE;
            mm_tile(curS, curS + AT_A_U32, wm0, wn0, g, q, c);
            if (more) {
                uint32_t* nx = sm + ((it + 1) & 1) * AT_STAGE;
                uint32_t* sa = nx;
                uint32_t* sb = nx + AT_A_U32;
                #pragma unroll
                for (int i = 0; i < 2; i++) {
                    const int base = (lr + i * 64) * SROW + lc4;
                    sa[base+0]=f2tf(ra[i].x); sa[base+8]=f2tf(ra[i].y);
                    sa[base+16]=f2tf(ra[i].z); sa[base+24]=f2tf(ra[i].w);
                }
                #pragma unroll
                for (int i = 0; i < 4; i++)
                    *(uint4*)&sb[(lr + i * 64) * SROW + lc4 * 4] = rbu[i];
                __syncthreads();
            }
        }

        #pragma unroll
        for (int mt = 0; mt < 2; mt++) {
            #pragma unroll
            for (int nt = 0; nt < 8; nt++) {
                const int n = col0 + wn0 + nt * 8 + q * 2;
                const float bb0 = bl[n], bb1 = bl[n + 1];
                rowsum[mt][0] += tanhf(c[mt][nt][0] + bb0) * gw[(long)rbi0[mt] * DD + n]
                               + tanhf(c[mt][nt][1] + bb1) * gw[(long)rbi0[mt] * DD + n + 1];
                rowsum[mt][1] += tanhf(c[mt][nt][2] + bb0) * gw[(long)rbi1[mt] * DD + n]
                               + tanhf(c[mt][nt][3] + bb1) * gw[(long)rbi1[mt] * DD + n + 1];
            }
        }
        __syncthreads();
    }

    const int rc = (wid >> 2) * 4 + q;   // 0..15
    #pragma unroll
    for (int mt = 0; mt < 2; mt++) {
        red[wm0 + mt * 16 + g    ][rc] = rowsum[mt][0];
        red[wm0 + mt * 16 + g + 8][rc] = rowsum[mt][1];
    }
    __syncthreads();
    if (tid < 128) {
        float s = 0.f;
        #pragma unroll
        for (int x = 0; x < 16; x++) s += red[tid][x];
        wraw[row0 + tid] = s + bc[0];
    }
}

// ---------------- small kernels ------------------------------------------------
__global__ void zero_htf(uint32_t* __restrict__ htf)
{
    const size_t i = (size_t)blockIdx.x * 256 + threadIdx.x;
    htf[i] = 0u;
}

__global__ void maxpool(const int* __restrict__ inds,
                        const float* __restrict__ y_word,
                        float* __restrict__ y_pool)
{
    const int idx = blockIdx.x * 256 + threadIdx.x;
    const int b = idx >> 10;
    const int d = idx & (DD - 1);
    float m = -INFINITY;
    #pragma unroll
    for (int t = 0; t < TT; t++) {
        if (inds[b * TT + t] != 0)
            m = fmaxf(m, y_word[(long)(b * TT + t) * DD + d]);
    }
    y_pool[idx] = m;
}

__global__ void softmax_out(const float* __restrict__ w_raw,
                            const float* __restrict__ y_word,
                            float* __restrict__ out)
{
    __shared__ float p[TT];
    const int b = blockIdx.x;
    if (threadIdx.x == 0) {
        float v[TT]; float mx = -INFINITY;
        #pragma unroll
        for (int t = 0; t < TT; t++) { v[t] = w_raw[b * TT + t]; mx = fmaxf(mx, v[t]); }
        float s = 0.f;
        #pragma unroll
        for (int t = 0; t < TT; t++) { v[t] = expf(v[t] - mx); s += v[t]; }
        const float inv = 1.f / s;
        #pragma unroll
        for (int t = 0; t < TT; t++) p[t] = v[t] * inv;
    }
    __syncthreads();
    for (int d = threadIdx.x; d < DD; d += 256) {
        float s = 0.f;
        #pragma unroll
        for (int t = 0; t < TT; t++)
            s += p[t] * y_word[((long)(b * TT + t)) * DD + d];
        out[(long)b * DD + d] = s;
    }
}

// ---------------- host launch --------------------------------------------------
extern "C" void kernel_launch(void* const* d_in, const int* in_sizes, int n_in,
                              void* d_out, int out_size)
{
    const int*   inds     = (const int*)  d_in[0];
    const float* emb      = (const float*)d_in[1];
    const float* w_ih_f   = (const float*)d_in[2];
    const float* w_hh_f   = (const float*)d_in[3];
    const float* b_ih_f   = (const float*)d_in[4];
    const float* b_hh_f   = (const float*)d_in[5];
    const float* w_ih_b   = (const float*)d_in[6];
    const float* w_hh_b   = (const float*)d_in[7];
    const float* b_ih_b   = (const float*)d_in[8];
    const float* b_hh_b   = (const float*)d_in[9];
    const float* w_local  = (const float*)d_in[10];
    const float* b_local  = (const float*)d_in[11];
    const float* w_global = (const float*)d_in[12];
    const float* b_global = (const float*)d_in[13];
    const float* w_common = (const float*)d_in[14];
    const float* b_common = (const float*)d_in[15];
    float* out = (float*)d_out;

    float *git_f, *git_b, *yw, *yp, *gw, *wraw;
    uint32_t *whht, *wlt, *htf;
    cudaGetSymbolAddress((void**)&git_f, g_git_f);
    cudaGetSymbolAddress((void**)&git_b, g_git_b);
    cudaGetSymbolAddress((void**)&whht, g_whht);
    cudaGetSymbolAddress((void**)&wlt,  g_wlt);
    cudaGetSymbolAddress((void**)&htf,  g_htf);
    cudaGetSymbolAddress((void**)&yw,   g_yword);
    cudaGetSymbolAddress((void**)&yp,   g_ypool);
    cudaGetSymbolAddress((void**)&gw,   g_gw);
    cudaGetSymbolAddress((void**)&wraw, g_wraw);

    cudaFuncSetAttribute(tgemm,    cudaFuncAttributeMaxDynamicSharedMemorySize, SMEM_B);
    cudaFuncSetAttribute(attn_w,   cudaFuncAttributeMaxDynamicSharedMemorySize, AT_SMEM);
    cudaFuncSetAttribute(rec_step, cudaFuncAttributeMaxDynamicSharedMemorySize, R_SMEM);

    // 0. weight prep (permuted tf32)
    prep_whh<<<(2 * G3 * HID) / 256, 256>>>(w_hh_f, w_hh_b, whht);
    prep_wl<<<(DD * DD) / 256, 256>>>(w_local, wlt);

    // 1. zero hidden-state tf32 buffers
    zero_htf<<<(2 * 2 * BH) / 256, 256>>>(htf);

    // 2. per-vocab gi table (incl. b_ih), both dirs
    dim3 gt_grid((VOCAB + 127) / 128, G3 / 128, 2);
    tgemm<<<gt_grid, 256, SMEM_B>>>(emb, emb, EMBD,
                                    w_ih_f, w_ih_b, b_ih_f, b_ih_b, nullptr,
                                    git_f, git_b, VOCAB, G3, EMBD, 0);

    // 3. fused bidirectional GRU recurrence (64x64 tiles, 2 CTAs/SM)
    dim3 rec_grid(BATCH / 64, HID / 64, 2);
    for (int t = 0; t < TT; t++) {
        rec_step<<<rec_grid, 256, R_SMEM>>>(inds, git_f, git_b, whht,
                                            b_hh_f, b_hh_b, htf, yw, t);
    }

    // 4. masked max pool
    maxpool<<<(BATCH * DD) / 256, 256>>>(inds, yw, yp);

    // 5. gw = tanh(y_pool @ w_global^T + b_global) * w_common
    dim3 gw_grid(BATCH / 128, DD / 128, 1);
    tgemm<<<gw_grid, 256, SMEM_B>>>(yp, yp, DD,
                                    w_global, w_global, b_global, b_global, w_common,
                                    gw, gw, BATCH, DD, DD, 1);

    // 6. fused l_emb -> tanh -> dot(gw) -> attention logits (M128 x N256, 512t)
    attn_w<<<BT / 128, 512, AT_SMEM>>>(yw, wlt, b_local, gw, b_common, wraw);

    // 7. softmax over T + weighted sum
    softmax_out<<<BATCH, 256>>>(wraw, yw, out);
}

// round 9
// speedup vs baseline: 1.6581x; 1.4352x over previous
#include <cuda_runtime.h>
#include <cuda_fp16.h>
#include <math.h>
#include <stdint.h>

#define BATCH 4096
#define TT    15
#define EMBD  300
#define HID   512
#define G3    1536
#define DD    1024
#define BT    (BATCH*TT)
#define VOCAB 12000
#define BH    (BATCH*HID)
#define VROWS 12032            // VOCAB padded to 128

#define KROW  20               // u32 per 32-k row chunk (16 fp16x2 + 4 pad)

// git GEMM: A(128)+B(128) rows/stage, 3 stages
#define GP_STAGE (256*KROW)
#define GP_SMEM  (3*GP_STAGE*4)     // 61440 B
// recurrence: A(64)+B(192) rows/stage, 3 stages
#define RC_STAGE (256*KROW)
#define RC_SMEM  (3*RC_STAGE*4)     // 61440 B
// gw: A(128)+B(128), 2 stages
#define GW_STAGE (256*KROW)
#define GW_SMEM  (2*GW_STAGE*4)     // 40960 B
// attn: A(128)+B(256), 2 stages
#define AT_STAGE (384*KROW)
#define AT_SMEM  (2*AT_STAGE*4)     // 61440 B

// ---------------- scratch -----------------------------------------------------
__device__ float    g_git_f[(size_t)VOCAB * G3];
__device__ float    g_git_b[(size_t)VOCAB * G3];
__device__ uint32_t g_embt[(size_t)10 * VROWS * 16];   // fp16x2 permuted emb (K pad 320)
__device__ uint32_t g_wiht[(size_t)2 * 10 * G3 * 16];  // fp16x2 permuted w_ih
__device__ uint32_t g_whht[(size_t)2 * 16 * G3 * 16];  // fp16x2 permuted w_hh
__device__ uint32_t g_wlt [(size_t)32 * DD * 16];      // fp16x2 permuted w_local
__device__ uint32_t g_wgt [(size_t)32 * DD * 16];      // fp16x2 permuted w_global
__device__ uint32_t g_htf [(size_t)2 * 2 * BATCH * 256]; // fp16x2 permuted h [dir][buf]
__device__ float    g_yword[(size_t)BT * DD];
__device__ float    g_ypool[BATCH * DD];
__device__ float    g_gw  [BATCH * DD];
__device__ float    g_wraw[BT];

// ---------------- helpers ------------------------------------------------------
__device__ __forceinline__ uint32_t pkh2(float lo, float hi) {
    __half2 h = __floats2half2_rn(lo, hi);
    return *(uint32_t*)&h;
}
__device__ __forceinline__ void mma16(float* c,
    uint32_t a0, uint32_t a1, uint32_t a2, uint32_t a3,
    uint32_t b0, uint32_t b1)
{
    asm volatile(
        "mma.sync.aligned.m16n8k16.row.col.f32.f16.f16.f32 "
        "{%0,%1,%2,%3},{%4,%5,%6,%7},{%8,%9},{%0,%1,%2,%3};"
        : "+f"(c[0]), "+f"(c[1]), "+f"(c[2]), "+f"(c[3])
        : "r"(a0), "r"(a1), "r"(a2), "r"(a3), "r"(b0), "r"(b1));
}
__device__ __forceinline__ float sigm(float x) { return 1.f / (1.f + expf(-x)); }
__device__ __forceinline__ void cp16(uint32_t saddr, const void* g) {
    asm volatile("cp.async.cg.shared.global [%0], [%1], 16;" :: "r"(saddr), "l"(g));
}

// 2 m16-tiles x NT n8-tiles for one k32 chunk (fragments pre-permuted in smem)
template<int NT>
__device__ __forceinline__ void mm16t(const uint32_t* As, const uint32_t* Bs,
    int wm0, int wn0, int g, int q, float c[][NT][4])
{
    const uint4* A4 = (const uint4*)As;   // row stride 5 uint4
    const uint4* B4 = (const uint4*)Bs;
    uint4 aL[2], aH[2], bu[NT];
    aL[0] = A4[(wm0 + g     ) * 5 + q];
    aH[0] = A4[(wm0 + g +  8) * 5 + q];
    aL[1] = A4[(wm0 + g + 16) * 5 + q];
    aH[1] = A4[(wm0 + g + 24) * 5 + q];
    #pragma unroll
    for (int nt = 0; nt < NT; nt++) bu[nt] = B4[(wn0 + nt * 8 + g) * 5 + q];
    #pragma unroll
    for (int mt = 0; mt < 2; mt++)
        #pragma unroll
        for (int nt = 0; nt < NT; nt++)
            mma16(c[mt][nt], aL[mt].x, aH[mt].x, aL[mt].y, aH[mt].y,
                  bu[nt].x, bu[nt].y);
    #pragma unroll
    for (int mt = 0; mt < 2; mt++)
        #pragma unroll
        for (int nt = 0; nt < NT; nt++)
            mma16(c[mt][nt], aL[mt].z, aH[mt].z, aL[mt].w, aH[mt].w,
                  bu[nt].z, bu[nt].w);
}

// ---------------- generic fp16 permuted-prep -----------------------------------
// out[(kc*Rout + r)*16 + slot] = half2(in[r,k0], in[r,k0+1]); slot<->kpair transpose
__global__ void prep_fp16(const float* __restrict__ in, uint32_t* __restrict__ out,
                          int R, int Rout, int K, int KC)
{
    const int idx = blockIdx.x * 256 + threadIdx.x;
    if (idx >= KC * Rout * 16) return;
    const int kc  = idx / (Rout * 16);
    const int rem = idx % (Rout * 16);
    const int r = rem >> 4, slot = rem & 15;
    const int kp = (slot & 3) * 4 + (slot >> 2);
    const int k0 = kc * 32 + kp * 2;
    const float v0 = (r < R && k0     < K) ? in[(size_t)r * K + k0]     : 0.f;
    const float v1 = (r < R && k0 + 1 < K) ? in[(size_t)r * K + k0 + 1] : 0.f;
    out[idx] = pkh2(v0, v1);
}

// ================= git GEMM: prepped x prepped, 3-stage cp.async ===============
__global__ void __launch_bounds__(256) hgemm_pp(
    const uint32_t* __restrict__ At,
    const uint32_t* __restrict__ Wt, const uint32_t* __restrict__ Wt2,
    const float* __restrict__ bias, const float* __restrict__ bias2,
    float* __restrict__ C, float* __restrict__ C2,
    int Mout, int Ar, int N, int KC)
{
    const uint32_t* W = Wt; const float* bi = bias; float* Co = C;
    if (blockIdx.z == 1) { W = Wt2; bi = bias2; Co = C2; }
    extern __shared__ uint32_t sm[];
    const uint32_t sbase = (uint32_t)__cvta_generic_to_shared(sm);

    const int tid  = threadIdx.x;
    const int lane = tid & 31, wid = tid >> 5;
    const int g = lane >> 2, q = lane & 3;
    const int wm0 = (wid & 3) * 32;
    const int wn0 = (wid >> 2) * 64;
    const int row0 = blockIdx.x * 128;
    const int col0 = blockIdx.y * 128;

    auto issue = [&](int kc, int st) {
        const uint32_t s0 = sbase + st * GP_STAGE * 4;
        #pragma unroll
        for (int s = 0; s < 2; s++) {
            const int u = tid + s * 256;
            const int r = u >> 2, j = u & 3;
            cp16(s0 + (r * KROW + j * 4) * 4,
                 At + ((size_t)kc * Ar + row0 + r) * 16 + j * 4);
        }
        #pragma unroll
        for (int s = 0; s < 2; s++) {
            const int u = tid + s * 256;
            const int r = u >> 2, j = u & 3;
            cp16(s0 + (128 * KROW + r * KROW + j * 4) * 4,
                 W + ((size_t)kc * N + col0 + r) * 16 + j * 4);
        }
        asm volatile("cp.async.commit_group;");
    };

    float c[2][8][4];
    #pragma unroll
    for (int mt = 0; mt < 2; mt++)
        #pragma unroll
        for (int nt = 0; nt < 8; nt++)
            #pragma unroll
            for (int j = 0; j < 4; j++) c[mt][nt][j] = 0.f;

    issue(0, 0);
    if (KC > 1) issue(1, 1);
    for (int it = 0; it < KC; it++) {
        if (it + 1 < KC) asm volatile("cp.async.wait_group 1;");
        else             asm volatile("cp.async.wait_group 0;");
        __syncthreads();
        if (it + 2 < KC) issue(it + 2, (it + 2) % 3);
        const uint32_t* curS = sm + (it % 3) * GP_STAGE;
        mm16t<8>(curS, curS + 128 * KROW, wm0, wn0, g, q, c);
        __syncthreads();
    }

    #pragma unroll
    for (int mt = 0; mt < 2; mt++) {
        const int r = row0 + wm0 + mt * 16 + g;
        #pragma unroll
        for (int nt = 0; nt < 8; nt++) {
            const int n = col0 + wn0 + nt * 8 + q * 2;
            const float b0 = bi[n], b1 = bi[n + 1];
            if (r < Mout)
                *(float2*)(Co + (size_t)r * N + n) =
                    make_float2(c[mt][nt][0] + b0, c[mt][nt][1] + b1);
            if (r + 8 < Mout)
                *(float2*)(Co + (size_t)(r + 8) * N + n) =
                    make_float2(c[mt][nt][2] + b0, c[mt][nt][3] + b1);
        }
    }
}

// ================= fused GRU recurrence step (fp16, cp.async) ==================
__global__ void __launch_bounds__(256, 2) rec_step(
    const int* __restrict__ inds,
    const float* __restrict__ git_f, const float* __restrict__ git_b,
    const uint32_t* __restrict__ whht,
    const float* __restrict__ bhh_f, const float* __restrict__ bhh_b,
    uint32_t* __restrict__ htf,
    float* __restrict__ y_word, int t)
{
    const int dir = blockIdx.z;
    const int cur = t & 1, nxt = cur ^ 1;
    const float* git = dir ? git_b : git_f;
    const float* bhh = dir ? bhh_b : bhh_f;
    const int tt  = dir ? (TT - 1 - t) : t;
    const int off = dir ? HID : 0;
    const uint32_t* Wp    = whht + (size_t)dir * 16 * G3 * 16;
    const uint32_t* hprev = htf + ((size_t)dir * 2 + cur) * BATCH * 256;
    uint32_t*       hnext = htf + ((size_t)dir * 2 + nxt) * BATCH * 256;

    extern __shared__ uint32_t sm[];
    const uint32_t sbase = (uint32_t)__cvta_generic_to_shared(sm);

    const int tid  = threadIdx.x;
    const int lane = tid & 31, wid = tid >> 5;
    const int g = lane >> 2, q = lane & 3;
    const int wm0 = (wid & 1) * 32;       // 2 m-warps
    const int wn0 = (wid >> 1) * 16;      // 4 n-warps (16 hid cols each)
    const int row0 = blockIdx.x * 64;
    const int col0 = blockIdx.y * 64;

    auto issue = [&](int kc, int st) {
        const uint32_t s0 = sbase + st * RC_STAGE * 4;
        {   // A: 64 rows x 4 units = 256
            const int r = tid >> 2, j = tid & 3;
            cp16(s0 + (r * KROW + j * 4) * 4,
                 hprev + (size_t)(row0 + r) * 256 + kc * 16 + j * 4);
        }
        #pragma unroll
        for (int s = 0; s < 3; s++) {     // B: 192 rows x 4 units = 768
            const int u = tid + s * 256;
            const int r = u >> 2, j = u & 3;
            const int gate = r >> 6, wi = r & 63;
            cp16(s0 + (64 * KROW + r * KROW + j * 4) * 4,
                 Wp + ((size_t)kc * G3 + gate * HID + col0 + wi) * 16 + j * 4);
        }
        asm volatile("cp.async.commit_group;");
    };

    float c[3][2][2][4];
    #pragma unroll
    for (int gt = 0; gt < 3; gt++)
        #pragma unroll
        for (int mt = 0; mt < 2; mt++)
            #pragma unroll
            for (int nt = 0; nt < 2; nt++)
                #pragma unroll
                for (int j = 0; j < 4; j++) c[gt][mt][nt][j] = 0.f;

    const int nk = HID / 32;  // 16
    issue(0, 0);
    issue(1, 1);

    for (int it = 0; it < nk; it++) {
        if (it + 1 < nk) asm volatile("cp.async.wait_group 1;");
        else             asm volatile("cp.async.wait_group 0;");
        __syncthreads();
        if (it + 2 < nk) issue(it + 2, (it + 2) % 3);

        const uint32_t* curS = sm + (it % 3) * RC_STAGE;
        const uint4* A4 = (const uint4*)curS;
        const uint4* B4 = (const uint4*)(curS + 64 * KROW);
        const uint4 aL0 = A4[(wm0 + g     ) * 5 + q];
        const uint4 aH0 = A4[(wm0 + g +  8) * 5 + q];
        const uint4 aL1 = A4[(wm0 + g + 16) * 5 + q];
        const uint4 aH1 = A4[(wm0 + g + 24) * 5 + q];
        uint4 bu[3][2];
        #pragma unroll
        for (int gt = 0; gt < 3; gt++)
            #pragma unroll
            for (int nt = 0; nt < 2; nt++)
                bu[gt][nt] = B4[(gt * 64 + wn0 + nt * 8 + g) * 5 + q];
        #pragma unroll
        for (int gt = 0; gt < 3; gt++)
            #pragma unroll
            for (int nt = 0; nt < 2; nt++) {
                mma16(c[gt][0][nt], aL0.x, aH0.x, aL0.y, aH0.y,
                      bu[gt][nt].x, bu[gt][nt].y);
                mma16(c[gt][1][nt], aL1.x, aH1.x, aL1.y, aH1.y,
                      bu[gt][nt].x, bu[gt][nt].y);
            }
        #pragma unroll
        for (int gt = 0; gt < 3; gt++)
            #pragma unroll
            for (int nt = 0; nt < 2; nt++) {
                mma16(c[gt][0][nt], aL0.z, aH0.z, aL0.w, aH0.w,
                      bu[gt][nt].z, bu[gt][nt].w);
                mma16(c[gt][1][nt], aL1.z, aH1.z, aL1.w, aH1.w,
                      bu[gt][nt].z, bu[gt][nt].w);
            }
        __syncthreads();
    }

    // ---- GRU cell epilogue ----
    #pragma unroll
    for (int mt = 0; mt < 2; mt++) {
        #pragma unroll
        for (int rr = 0; rr < 2; rr++) {
            const int b = row0 + wm0 + mt * 16 + g + rr * 8;
            const int tok = inds[b * TT + tt];
            const float* gib = git + (size_t)tok * G3;
            #pragma unroll
            for (int nt = 0; nt < 2; nt++) {
                const int hg = col0 + wn0 + nt * 8 + q * 2;   // even
                const int j0 = rr * 2;
                const int kpair = (hg & 31) >> 1;
                const int slot = (kpair & 3) * 4 + (kpair >> 2);
                const size_t hw = (size_t)b * 256 + (hg >> 5) * 16 + slot;
                const __half2 hp2 = *(const __half2*)&hprev[hw];
                float hn2[2];
                #pragma unroll
                for (int e = 0; e < 2; e++) {
                    const int hh = hg + e;
                    const float gir = gib[hh];
                    const float giz = gib[HID + hh];
                    const float gin = gib[2 * HID + hh];
                    const float ghr = c[0][mt][nt][j0 + e] + bhh[hh];
                    const float ghz = c[1][mt][nt][j0 + e] + bhh[HID + hh];
                    const float ghn = c[2][mt][nt][j0 + e] + bhh[2 * HID + hh];
                    const float hp = (e == 0) ? __low2float(hp2) : __high2float(hp2);
                    const float r = sigm(gir + ghr);
                    const float z = sigm(giz + ghz);
                    const float n = tanhf(gin + r * ghn);
                    hn2[e] = (1.f - z) * n + z * hp;
                }
                hnext[hw] = pkh2(hn2[0], hn2[1]);
                *(float2*)(y_word + (size_t)(b * TT + tt) * DD + off + hg) =
                    make_float2(hn2[0], hn2[1]);
            }
        }
    }
}

// ================= gw GEMM: fp32-A convert x prepped-B =========================
__global__ void __launch_bounds__(256) hgemm_gw(
    const float* __restrict__ A, const uint32_t* __restrict__ Wt,
    const float* __restrict__ bias, const float* __restrict__ wc,
    float* __restrict__ C)
{
    extern __shared__ uint32_t sm[];
    const int tid  = threadIdx.x;
    const int lane = tid & 31, wid = tid >> 5;
    const int g = lane >> 2, q = lane & 3;
    const int wm0 = (wid & 3) * 32;
    const int wn0 = (wid >> 2) * 64;
    const int row0 = blockIdx.x * 128;
    const int col0 = blockIdx.y * 128;
    const int sr = tid >> 1;               // staging row 0..127
    const int j0s = (tid & 1) * 2;         // block pair

    const float* arow = A + (size_t)(row0 + sr) * DD;

    auto stageA = [&](uint32_t* sa, int kc) {
        #pragma unroll
        for (int jj = 0; jj < 2; jj++) {
            const int j = j0s + jj;
            const float* p = arow + kc * 32 + 2 * j;
            const float2 f0 = *(const float2*)(p);
            const float2 f1 = *(const float2*)(p + 8);
            const float2 f2 = *(const float2*)(p + 16);
            const float2 f3 = *(const float2*)(p + 24);
            uint4 w;
            w.x = pkh2(f0.x, f0.y); w.y = pkh2(f1.x, f1.y);
            w.z = pkh2(f2.x, f2.y); w.w = pkh2(f3.x, f3.y);
            *(uint4*)&sa[sr * KROW + j * 4] = w;
        }
    };
    auto stageB = [&](uint32_t* sb, const uint4* rbu) {
        #pragma unroll
        for (int jj = 0; jj < 2; jj++)
            *(uint4*)&sb[sr * KROW + (j0s + jj) * 4] = rbu[jj];
    };
    auto loadB = [&](uint4* rbu, int kc) {
        #pragma unroll
        for (int jj = 0; jj < 2; jj++)
            rbu[jj] = *(const uint4*)(Wt + ((size_t)kc * DD + col0 + sr) * 16
                                          + (j0s + jj) * 4);
    };

    float c[2][8][4];
    #pragma unroll
    for (int mt = 0; mt < 2; mt++)
        #pragma unroll
        for (int nt = 0; nt < 8; nt++)
            #pragma unroll
            for (int j = 0; j < 4; j++) c[mt][nt][j] = 0.f;

    const int nk = DD / 32;  // 32
    uint4 rbu[2];
    loadB(rbu, 0);
    stageA(sm, 0);
    stageB(sm + 128 * KROW, rbu);
    __syncthreads();

    for (int it = 0; it < nk; it++) {
        const bool more = (it + 1 < nk);
        if (more) loadB(rbu, it + 1);
        const uint32_t* curS = sm + (it & 1) * GW_STAGE;
        mm16t<8>(curS, curS + 128 * KROW, wm0, wn0, g, q, c);
        if (more) {
            uint32_t* nx = sm + ((it + 1) & 1) * GW_STAGE;
            stageA(nx, it + 1);
            stageB(nx + 128 * KROW, rbu);
            __syncthreads();
        }
    }

    #pragma unroll
    for (int mt = 0; mt < 2; mt++) {
        const int r = row0 + wm0 + mt * 16 + g;
        #pragma unroll
        for (int nt = 0; nt < 8; nt++) {
            const int n = col0 + wn0 + nt * 8 + q * 2;
            const float b0 = bias[n], b1 = bias[n + 1];
            const float w0 = wc[n], w1 = wc[n + 1];
            *(float2*)(C + (size_t)r * DD + n) =
                make_float2(tanhf(c[mt][nt][0] + b0) * w0,
                            tanhf(c[mt][nt][1] + b1) * w1);
            *(float2*)(C + (size_t)(r + 8) * DD + n) =
                make_float2(tanhf(c[mt][nt][2] + b0) * w0,
                            tanhf(c[mt][nt][3] + b1) * w1);
        }
    }
}

// ================= fused attention logits: 512t, M128 x N256/pass ==============
__global__ void __launch_bounds__(512) attn_w(
    const float* __restrict__ yw, const uint32_t* __restrict__ wlt,
    const float* __restrict__ bl, const float* __restrict__ gw,
    const float* __restrict__ bc, float* __restrict__ wraw)
{
    extern __shared__ uint32_t sm[];
    __shared__ float red[128][17];

    const int tid  = threadIdx.x;
    const int lane = tid & 31, wid = tid >> 5;       // 0..15
    const int g = lane >> 2, q = lane & 3;
    const int wm0 = (wid & 3) * 32;
    const int wn0 = (wid >> 2) * 64;
    const int row0 = blockIdx.x * 128;
    const int ar = tid >> 2, aj = tid & 3;           // A: 1 block/thread
    const int br = tid >> 1, bj0 = (tid & 1) * 2;    // B: 2 blocks/thread

    const float* arow = yw + (size_t)(row0 + ar) * DD;

    auto stageA = [&](uint32_t* sa, int kc) {
        const float* p = arow + kc * 32 + 2 * aj;
        const float2 f0 = *(const float2*)(p);
        const float2 f1 = *(const float2*)(p + 8);
        const float2 f2 = *(const float2*)(p + 16);
        const float2 f3 = *(const float2*)(p + 24);
        uint4 w;
        w.x = pkh2(f0.x, f0.y); w.y = pkh2(f1.x, f1.y);
        w.z = pkh2(f2.x, f2.y); w.w = pkh2(f3.x, f3.y);
        *(uint4*)&sa[ar * KROW + aj * 4] = w;
    };
    auto loadB = [&](uint4* rbu, int kc, int col0) {
        #pragma unroll
        for (int jj = 0; jj < 2; jj++)
            rbu[jj] = *(const uint4*)(wlt + ((size_t)kc * DD + col0 + br) * 16
                                           + (bj0 + jj) * 4);
    };
    auto stageB = [&](uint32_t* sb, const uint4* rbu) {
        #pragma unroll
        for (int jj = 0; jj < 2; jj++)
            *(uint4*)&sb[br * KROW + (bj0 + jj) * 4] = rbu[jj];
    };

    int rbi0[2], rbi1[2];
    #pragma unroll
    for (int mt = 0; mt < 2; mt++) {
        const int r = row0 + wm0 + mt * 16 + g;
        rbi0[mt] = r / TT;
        rbi1[mt] = (r + 8) / TT;
    }
    float rowsum[2][2] = {{0.f, 0.f}, {0.f, 0.f}};

    const int nk = DD / 32;   // 32

    for (int ct = 0; ct < DD / 256; ct++) {
        const int col0 = ct * 256;

        float c[2][8][4];
        #pragma unroll
        for (int mt = 0; mt < 2; mt++)
            #pragma unroll
            for (int nt = 0; nt < 8; nt++)
                #pragma unroll
                for (int j = 0; j < 4; j++) c[mt][nt][j] = 0.f;

        uint4 rbu[2];
        loadB(rbu, 0, col0);
        stageA(sm, 0);
        stageB(sm + 128 * KROW, rbu);
        __syncthreads();

        for (int it = 0; it < nk; it++) {
            const bool more = (it + 1 < nk);
            if (more) loadB(rbu, it + 1, col0);
            const uint32_t* curS = sm + (it & 1) * AT_STAGE;
            mm16t<8>(curS, curS + 128 * KROW, wm0, wn0, g, q, c);
            if (more) {
                uint32_t* nx = sm + ((it + 1) & 1) * AT_STAGE;
                stageA(nx, it + 1);
                stageB(nx + 128 * KROW, rbu);
                __syncthreads();
            }
        }

        #pragma unroll
        for (int mt = 0; mt < 2; mt++) {
            #pragma unroll
            for (int nt = 0; nt < 8; nt++) {
                const int n = col0 + wn0 + nt * 8 + q * 2;
                const float bb0 = bl[n], bb1 = bl[n + 1];
                rowsum[mt][0] += tanhf(c[mt][nt][0] + bb0) * gw[(size_t)rbi0[mt] * DD + n]
                               + tanhf(c[mt][nt][1] + bb1) * gw[(size_t)rbi0[mt] * DD + n + 1];
                rowsum[mt][1] += tanhf(c[mt][nt][2] + bb0) * gw[(size_t)rbi1[mt] * DD + n]
                               + tanhf(c[mt][nt][3] + bb1) * gw[(size_t)rbi1[mt] * DD + n + 1];
            }
        }
        __syncthreads();
    }

    const int rc = (wid >> 2) * 4 + q;   // 0..15
    #pragma unroll
    for (int mt = 0; mt < 2; mt++) {
        red[wm0 + mt * 16 + g    ][rc] = rowsum[mt][0];
        red[wm0 + mt * 16 + g + 8][rc] = rowsum[mt][1];
    }
    __syncthreads();
    if (tid < 128) {
        float s = 0.f;
        #pragma unroll
        for (int x = 0; x < 16; x++) s += red[tid][x];
        wraw[row0 + tid] = s + bc[0];
    }
}

// ---------------- small kernels ------------------------------------------------
__global__ void zero_htf(uint32_t* __restrict__ htf)
{
    const size_t i = (size_t)blockIdx.x * 256 + threadIdx.x;
    htf[i] = 0u;
}

__global__ void maxpool(const int* __restrict__ inds,
                        const float* __restrict__ y_word,
                        float* __restrict__ y_pool)
{
    const int idx = blockIdx.x * 256 + threadIdx.x;
    const int b = idx >> 10;
    const int d = idx & (DD - 1);
    float m = -INFINITY;
    #pragma unroll
    for (int t = 0; t < TT; t++) {
        if (inds[b * TT + t] != 0)
            m = fmaxf(m, y_word[(size_t)(b * TT + t) * DD + d]);
    }
    y_pool[idx] = m;
}

__global__ void softmax_out(const float* __restrict__ w_raw,
                            const float* __restrict__ y_word,
                            float* __restrict__ out)
{
    __shared__ float p[TT];
    const int b = blockIdx.x;
    if (threadIdx.x == 0) {
        float v[TT]; float mx = -INFINITY;
        #pragma unroll
        for (int t = 0; t < TT; t++) { v[t] = w_raw[b * TT + t]; mx = fmaxf(mx, v[t]); }
        float s = 0.f;
        #pragma unroll
        for (int t = 0; t < TT; t++) { v[t] = expf(v[t] - mx); s += v[t]; }
        const float inv = 1.f / s;
        #pragma unroll
        for (int t = 0; t < TT; t++) p[t] = v[t] * inv;
    }
    __syncthreads();
    for (int d = threadIdx.x; d < DD; d += 256) {
        float s = 0.f;
        #pragma unroll
        for (int t = 0; t < TT; t++)
            s += p[t] * y_word[((size_t)(b * TT + t)) * DD + d];
        out[(size_t)b * DD + d] = s;
    }
}

// ---------------- host launch --------------------------------------------------
extern "C" void kernel_launch(void* const* d_in, const int* in_sizes, int n_in,
                              void* d_out, int out_size)
{
    const int*   inds     = (const int*)  d_in[0];
    const float* emb      = (const float*)d_in[1];
    const float* w_ih_f   = (const float*)d_in[2];
    const float* w_hh_f   = (const float*)d_in[3];
    const float* b_ih_f   = (const float*)d_in[4];
    const float* b_hh_f   = (const float*)d_in[5];
    const float* w_ih_b   = (const float*)d_in[6];
    const float* w_hh_b   = (const float*)d_in[7];
    const float* b_ih_b   = (const float*)d_in[8];
    const float* b_hh_b   = (const float*)d_in[9];
    const float* w_local  = (const float*)d_in[10];
    const float* b_local  = (const float*)d_in[11];
    const float* w_global = (const float*)d_in[12];
    const float* b_global = (const float*)d_in[13];
    const float* w_common = (const float*)d_in[14];
    const float* b_common = (const float*)d_in[15];
    float* out = (float*)d_out;

    float *git_f, *git_b, *yw, *yp, *gw, *wraw;
    uint32_t *embt, *wiht, *whht, *wlt, *wgt, *htf;
    cudaGetSymbolAddress((void**)&git_f, g_git_f);
    cudaGetSymbolAddress((void**)&git_b, g_git_b);
    cudaGetSymbolAddress((void**)&embt, g_embt);
    cudaGetSymbolAddress((void**)&wiht, g_wiht);
    cudaGetSymbolAddress((void**)&whht, g_whht);
    cudaGetSymbolAddress((void**)&wlt,  g_wlt);
    cudaGetSymbolAddress((void**)&wgt,  g_wgt);
    cudaGetSymbolAddress((void**)&htf,  g_htf);
    cudaGetSymbolAddress((void**)&yw,   g_yword);
    cudaGetSymbolAddress((void**)&yp,   g_ypool);
    cudaGetSymbolAddress((void**)&gw,   g_gw);
    cudaGetSymbolAddress((void**)&wraw, g_wraw);

    cudaFuncSetAttribute(hgemm_pp, cudaFuncAttributeMaxDynamicSharedMemorySize, GP_SMEM);
    cudaFuncSetAttribute(rec_step, cudaFuncAttributeMaxDynamicSharedMemorySize, RC_SMEM);
    cudaFuncSetAttribute(hgemm_gw, cudaFuncAttributeMaxDynamicSharedMemorySize, GW_SMEM);
    cudaFuncSetAttribute(attn_w,   cudaFuncAttributeMaxDynamicSharedMemorySize, AT_SMEM);

    // 0. one-time preps (permuted fp16x2)
    auto nb = [](long n) { return (int)((n + 255) / 256); };
    prep_fp16<<<nb((long)10 * VROWS * 16), 256>>>(emb, embt, VOCAB, VROWS, EMBD, 10);
    prep_fp16<<<nb((long)10 * G3 * 16), 256>>>(w_ih_f, wiht, G3, G3, EMBD, 10);
    prep_fp16<<<nb((long)10 * G3 * 16), 256>>>(w_ih_b, wiht + (size_t)10 * G3 * 16, G3, G3, EMBD, 10);
    prep_fp16<<<nb((long)16 * G3 * 16), 256>>>(w_hh_f, whht, G3, G3, HID, 16);
    prep_fp16<<<nb((long)16 * G3 * 16), 256>>>(w_hh_b, whht + (size_t)16 * G3 * 16, G3, G3, HID, 16);
    prep_fp16<<<nb((long)32 * DD * 16), 256>>>(w_local,  wlt, DD, DD, DD, 32);
    prep_fp16<<<nb((long)32 * DD * 16), 256>>>(w_global, wgt, DD, DD, DD, 32);

    // 1. zero hidden-state buffers
    zero_htf<<<(2 * 2 * BATCH * 256) / 256, 256>>>(htf);

    // 2. per-vocab gi table (incl. b_ih), both dirs
    dim3 gt_grid(VROWS / 128, G3 / 128, 2);
    hgemm_pp<<<gt_grid, 256, GP_SMEM>>>(embt, wiht, wiht + (size_t)10 * G3 * 16,
                                        b_ih_f, b_ih_b, git_f, git_b,
                                        VOCAB, VROWS, G3, 10);

    // 3. fused bidirectional GRU recurrence
    dim3 rec_grid(BATCH / 64, HID / 64, 2);
    for (int t = 0; t < TT; t++) {
        rec_step<<<rec_grid, 256, RC_SMEM>>>(inds, git_f, git_b, whht,
                                             b_hh_f, b_hh_b, htf, yw, t);
    }

    // 4. masked max pool
    maxpool<<<(BATCH * DD) / 256, 256>>>(inds, yw, yp);

    // 5. gw = tanh(y_pool @ w_global^T + b_global) * w_common
    dim3 gw_grid(BATCH / 128, DD / 128, 1);
    hgemm_gw<<<gw_grid, 256, GW_SMEM>>>(yp, wgt, b_global, w_common, gw);

    // 6. fused l_emb -> tanh -> dot(gw) -> attention logits
    attn_w<<<BT / 128, 512, AT_SMEM>>>(yw, wlt, b_local, gw, b_common, wraw);

    // 7. softmax over T + weighted sum
    softmax_out<<<BATCH, 256>>>(wraw, yw, out);
}